// round 7
// baseline (speedup 1.0000x reference)
#include <cuda_runtime.h>
#include <cuda_bf16.h>
#include <cstdint>

// ============================================================================
// KLinear: y[i,n] = (sum_k kron(a_k,b_k)[i,j] / (2*sqrt(8))) * x[n,j] + bias[n]
//
// tcgen05 is NOT available (harness PTX target is non-'a' sm_103), so the GEMM
// uses base-PTX tensor-core ops: mma.sync.m16n8k16 bf16 + ldmatrix + cp.async.
//
//   1) build W (fp32) -> split into bf16 hi/lo   (g_Whi, g_Wlo)
//   2) split X into bf16 hi/lo                   (g_Xhi, g_Xlo)
//   3) bf16 GEMM, 3-product split: Whi*Xhi + Whi*Xlo + Wlo*Xhi, fp32 accum.
//      128x128 tile/CTA, 8 warps (4x2), warp tile 32x64, KTILE=64,
//      SW128 swizzled smem, 3-stage cp.async pipeline.
// ============================================================================

#define N_DIM 4096
#define KTILE 64

// ---------------- scratch (device globals; no runtime allocation) ----------
__device__ __nv_bfloat16 g_Whi[(size_t)N_DIM * N_DIM];
__device__ __nv_bfloat16 g_Wlo[(size_t)N_DIM * N_DIM];
__device__ __nv_bfloat16 g_Xhi[(size_t)N_DIM * N_DIM];
__device__ __nv_bfloat16 g_Xlo[(size_t)N_DIM * N_DIM];

// ---------------- helpers ---------------------------------------------------
#define SMEM_SWIZZLE_128B(o) ((o) ^ (((o) >> 3) & 0x70))

__device__ __forceinline__ uint32_t smem_u32(const void* p) {
    uint32_t a;
    asm("{ .reg .u64 t; cvta.to.shared.u64 t, %1; cvt.u32.u64 %0, t; }"
        : "=r"(a) : "l"(p));
    return a;
}

__device__ __forceinline__ void cp_async16(uint32_t dst, const void* src) {
    asm volatile("cp.async.cg.shared.global [%0], [%1], 16;"
                 :: "r"(dst), "l"(src) : "memory");
}

__device__ __forceinline__ void ldm_x4(uint32_t (&r)[4], uint32_t addr) {
    asm volatile("ldmatrix.sync.aligned.m8n8.x4.shared.b16 {%0,%1,%2,%3}, [%4];"
                 : "=r"(r[0]), "=r"(r[1]), "=r"(r[2]), "=r"(r[3])
                 : "r"(addr));
}

__device__ __forceinline__ void mma_bf16(float (&d)[4], const uint32_t (&a)[4],
                                         uint32_t b0, uint32_t b1) {
    asm volatile(
        "mma.sync.aligned.m16n8k16.row.col.f32.bf16.bf16.f32 "
        "{%0,%1,%2,%3}, {%4,%5,%6,%7}, {%8,%9}, {%0,%1,%2,%3};"
        : "+f"(d[0]), "+f"(d[1]), "+f"(d[2]), "+f"(d[3])
        : "r"(a[0]), "r"(a[1]), "r"(a[2]), "r"(a[3]), "r"(b0), "r"(b1));
}

// ---------------- kernel 1: build W and split into bf16 hi/lo --------------
__global__ __launch_bounds__(256) void build_w_kernel(
    const float* __restrict__ a0, const float* __restrict__ a1,
    const float* __restrict__ a2, const float* __restrict__ a3,
    const float* __restrict__ a4, const float* __restrict__ a5,
    const float* __restrict__ a6, const float* __restrict__ a7,
    const float* __restrict__ b0, const float* __restrict__ b1,
    const float* __restrict__ b2, const float* __restrict__ b3,
    const float* __restrict__ b4, const float* __restrict__ b5,
    const float* __restrict__ b6, const float* __restrict__ b7)
{
    const int idx = blockIdx.x * blockDim.x + threadIdx.x;  // 0 .. 16.7M-1
    const int i = idx >> 12;
    const int j = idx & 4095;

    float s = 0.0f;
    s += a0[(i >> 6) * 64 + (j >> 6)] * b0[(i & 63) * 64 + (j & 63)];
    s += a1[(i >> 6) * 64 + (j >> 6)] * b1[(i & 63) * 64 + (j & 63)];
    s += a2[(i >> 7) * 32 + (j >> 7)] * b2[(i & 127) * 128 + (j & 127)];
    s += a3[(i >> 5) * 128 + (j >> 5)] * b3[(i & 31) * 32 + (j & 31)];
    s += a4[(i >> 8) * 16 + (j >> 8)] * b4[(i & 255) * 256 + (j & 255)];
    s += a5[(i >> 4) * 256 + (j >> 4)] * b5[(i & 15) * 16 + (j & 15)];
    s += a6[(i >> 9) * 8 + (j >> 9)] * b6[(i & 511) * 512 + (j & 511)];
    s += a7[(i >> 3) * 512 + (j >> 3)] * b7[(i & 7) * 8 + (j & 7)];

    s *= 0.17677669529663687f;  // 1 / (2*sqrt(8))

    __nv_bfloat16 hi = __float2bfloat16(s);
    g_Whi[idx] = hi;
    g_Wlo[idx] = __float2bfloat16(s - __bfloat162float(hi));
}

// ---------------- kernel 2: split X into bf16 hi/lo ------------------------
__global__ __launch_bounds__(256) void split_x_kernel(const float* __restrict__ x)
{
    const int i = blockIdx.x * blockDim.x + threadIdx.x;  // float4 index
    float4 v = reinterpret_cast<const float4*>(x)[i];

    __nv_bfloat16 hx = __float2bfloat16(v.x);
    __nv_bfloat16 hy = __float2bfloat16(v.y);
    __nv_bfloat16 hz = __float2bfloat16(v.z);
    __nv_bfloat16 hw = __float2bfloat16(v.w);

    __nv_bfloat162 h0; h0.x = hx; h0.y = hy;
    __nv_bfloat162 h1; h1.x = hz; h1.y = hw;

    __nv_bfloat162 l0, l1;
    l0.x = __float2bfloat16(v.x - __bfloat162float(hx));
    l0.y = __float2bfloat16(v.y - __bfloat162float(hy));
    l1.x = __float2bfloat16(v.z - __bfloat162float(hz));
    l1.y = __float2bfloat16(v.w - __bfloat162float(hw));

    reinterpret_cast<__nv_bfloat162*>(g_Xhi)[2 * i]     = h0;
    reinterpret_cast<__nv_bfloat162*>(g_Xhi)[2 * i + 1] = h1;
    reinterpret_cast<__nv_bfloat162*>(g_Xlo)[2 * i]     = l0;
    reinterpret_cast<__nv_bfloat162*>(g_Xlo)[2 * i + 1] = l1;
}

// ---------------- kernel 3: mma.sync bf16-split GEMM ------------------------
// SMEM: 3 stages x 64KB:
//   +0      W_hi (128 x 64 bf16, SW128-swizzled 128B rows)
//   +16384  W_lo
//   +32768  X_hi
//   +49152  X_lo
static constexpr int SM_BUFSZ   = 65536;
static constexpr int NSTAGE     = 3;
static constexpr int SMEM_TOTAL = NSTAGE * SM_BUFSZ;  // 196608

__global__ __launch_bounds__(256, 1)
void gemm_kernel(const float* __restrict__ bias, float* __restrict__ out)
{
    extern __shared__ __align__(1024) char smem[];
    const uint32_t sb = smem_u32(smem);
    const int tid = threadIdx.x;
    const int wid = tid >> 5;
    const int lid = tid & 31;

    const int rbase = blockIdx.x * 128;  // M rows (W / OUTF)
    const int nbase = blockIdx.y * 128;  // N rows (X / BATCH)

    const int warp_m = wid & 3;   // 0..3 -> 32-row slab
    const int warp_n = wid >> 2;  // 0..1 -> 64-col slab

    // per-lane ldmatrix addressing pieces
    const int lj  = lid & 7;   // row-within-8
    const int lsel = lid >> 3; // which 8x8 matrix this lane feeds

    // ---- cp.async stage loader -------------------------------------------
    auto load_stage = [&](int t) {
        if (t < 64) {
            const uint32_t bufb = sb + (uint32_t)(t % NSTAGE) * SM_BUFSZ;
            const int k0 = t * KTILE;
#pragma unroll
            for (int s = 0; s < 4; ++s) {
                const int c    = tid + s * 256;  // 0..1023
                const int row  = c >> 3;         // 0..127
                const int ch   = c & 7;          // 16B chunk in row
                const uint32_t sw =
                    SMEM_SWIZZLE_128B((uint32_t)(row * 128 + ch * 16));
                const size_t gW = (size_t)(rbase + row) * N_DIM + k0 + ch * 8;
                const size_t gX = (size_t)(nbase + row) * N_DIM + k0 + ch * 8;
                cp_async16(bufb + sw,         g_Whi + gW);
                cp_async16(bufb + 16384 + sw, g_Wlo + gW);
                cp_async16(bufb + 32768 + sw, g_Xhi + gX);
                cp_async16(bufb + 49152 + sw, g_Xlo + gX);
            }
        }
        asm volatile("cp.async.commit_group;" ::: "memory");
    };

    // ---- accumulators: 2 m-blocks x 8 n8-blocks x 4 regs -------------------
    float d[2][8][4];
#pragma unroll
    for (int mb = 0; mb < 2; ++mb)
#pragma unroll
        for (int nb = 0; nb < 8; ++nb)
#pragma unroll
            for (int r = 0; r < 4; ++r) d[mb][nb][r] = 0.0f;

    // prologue: stages 0 and 1 in flight
    load_stage(0);
    load_stage(1);

    for (int t = 0; t < 64; ++t) {
        // group t must be complete (<=1 newer groups pending)
        asm volatile("cp.async.wait_group 1;" ::: "memory");
        __syncthreads();

        // issue stage t+2 (overwrites the buffer compute t-1 used)
        load_stage(t + 2);

        const uint32_t bufb = sb + (uint32_t)(t % NSTAGE) * SM_BUFSZ;
        const uint32_t aHi = bufb;
        const uint32_t aLo = bufb + 16384;
        const uint32_t xHi = bufb + 32768;
        const uint32_t xLo = bufb + 49152;

#pragma unroll
        for (int ks = 0; ks < 4; ++ks) {
            const int kc = ks * 2;  // 16B-chunk index of this k16 step

            // A fragments: rows = M. x4 matrices: (m0-7,k0), (m8-15,k0),
            //                                    (m0-7,k1), (m8-15,k1)
            uint32_t ah[2][4], al[2][4];
#pragma unroll
            for (int mb = 0; mb < 2; ++mb) {
                const int row = warp_m * 32 + mb * 16 + lj + ((lsel & 1) << 3);
                const int ch  = kc + (lsel >> 1);
                const uint32_t off =
                    SMEM_SWIZZLE_128B((uint32_t)(row * 128 + ch * 16));
                ldm_x4(ah[mb], aHi + off);
                ldm_x4(al[mb], aLo + off);
            }

            // B fragments: rows = N. x4 matrices: (n0-7,k0), (n0-7,k1),
            //                                    (n8-15,k0), (n8-15,k1)
            uint32_t bh[4][4], bl[4][4];
#pragma unroll
            for (int nb = 0; nb < 4; ++nb) {
                const int row = warp_n * 64 + nb * 16 + lj + ((lsel >> 1) << 3);
                const int ch  = kc + (lsel & 1);
                const uint32_t off =
                    SMEM_SWIZZLE_128B((uint32_t)(row * 128 + ch * 16));
                ldm_x4(bh[nb], xHi + off);
                ldm_x4(bl[nb], xLo + off);
            }

            // 3-product split MMAs
#pragma unroll
            for (int mb = 0; mb < 2; ++mb) {
#pragma unroll
                for (int nb = 0; nb < 4; ++nb) {
                    mma_bf16(d[mb][nb * 2 + 0], ah[mb], bh[nb][0], bh[nb][1]);
                    mma_bf16(d[mb][nb * 2 + 1], ah[mb], bh[nb][2], bh[nb][3]);
                    mma_bf16(d[mb][nb * 2 + 0], ah[mb], bl[nb][0], bl[nb][1]);
                    mma_bf16(d[mb][nb * 2 + 1], ah[mb], bl[nb][2], bl[nb][3]);
                    mma_bf16(d[mb][nb * 2 + 0], al[mb], bh[nb][0], bh[nb][1]);
                    mma_bf16(d[mb][nb * 2 + 1], al[mb], bh[nb][2], bh[nb][3]);
                }
            }
        }
    }

    // drain remaining (empty) groups
    asm volatile("cp.async.wait_group 0;" ::: "memory");

    // ---- epilogue: regs -> gmem (+bias) ------------------------------------
    // mma d-frag: d0,d1 -> row (lid>>2), cols (lid&3)*2 + {0,1}
    //             d2,d3 -> row (lid>>2)+8, same cols
    const int rw = rbase + warp_m * 32 + (lid >> 2);
    const int cw = nbase + warp_n * 64 + (lid & 3) * 2;
#pragma unroll
    for (int mb = 0; mb < 2; ++mb) {
#pragma unroll
        for (int nb = 0; nb < 8; ++nb) {
            const int col = cw + nb * 8;
            const float b0 = __ldg(bias + col);
            const float b1 = __ldg(bias + col + 1);
            const int r0 = rw + mb * 16;
            float2 v0, v1;
            v0.x = d[mb][nb][0] + b0;
            v0.y = d[mb][nb][1] + b1;
            v1.x = d[mb][nb][2] + b0;
            v1.y = d[mb][nb][3] + b1;
            *reinterpret_cast<float2*>(out + (size_t)r0 * N_DIM + col) = v0;
            *reinterpret_cast<float2*>(out + (size_t)(r0 + 8) * N_DIM + col) = v1;
        }
    }
}

// ---------------- launch ----------------------------------------------------
extern "C" void kernel_launch(void* const* d_in, const int* in_sizes, int n_in,
                              void* d_out, int out_size)
{
    const float* x    = (const float*)d_in[0];
    const float* a[8] = {(const float*)d_in[1], (const float*)d_in[2],
                         (const float*)d_in[3], (const float*)d_in[4],
                         (const float*)d_in[5], (const float*)d_in[6],
                         (const float*)d_in[7], (const float*)d_in[8]};
    const float* b[8] = {(const float*)d_in[9],  (const float*)d_in[10],
                         (const float*)d_in[11], (const float*)d_in[12],
                         (const float*)d_in[13], (const float*)d_in[14],
                         (const float*)d_in[15], (const float*)d_in[16]};
    const float* bias = (const float*)d_in[17];
    float* out = (float*)d_out;

    cudaFuncSetAttribute(gemm_kernel,
                         cudaFuncAttributeMaxDynamicSharedMemorySize,
                         SMEM_TOTAL);

    // 1) W build + split
    build_w_kernel<<<(N_DIM * N_DIM) / 256, 256>>>(
        a[0], a[1], a[2], a[3], a[4], a[5], a[6], a[7],
        b[0], b[1], b[2], b[3], b[4], b[5], b[6], b[7]);

    // 2) X split (float4-vectorized)
    split_x_kernel<<<(N_DIM * N_DIM / 4) / 256, 256>>>(x);

    // 3) GEMM: 32x32 grid of 128x128 tiles
    gemm_kernel<<<dim3(32, 32), 256, SMEM_TOTAL>>>(bias, out);
}

// round 8
// speedup vs baseline: 1.0102x; 1.0102x over previous
#include <cuda_runtime.h>
#include <cuda_bf16.h>
#include <cstdint>

// ============================================================================
// KLinear: y[i,n] = (sum_k kron(a_k,b_k)[i,j] / (2*sqrt(8))) * x[n,j] + bias[n]
//
// tcgen05 unavailable (harness PTX target = compute_103, no 'a' features);
// GEMM uses base-PTX mma.sync.m16n8k16 bf16 + ldmatrix + cp.async.
//
//   1) build W -> bf16 hi/lo (vectorized 8 outputs/thread)
//   2) split X -> bf16 hi/lo
//   3) bf16 GEMM, 3-product split (Whi*Xhi + Whi*Xlo + Wlo*Xhi), fp32 accum.
//      128x128 CTA tile, 16 warps (4x4), 32x32 warp tile, KTILE=64,
//      SW128 swizzled smem, 3-stage cp.async pipeline.
// ============================================================================

#define N_DIM 4096
#define KTILE 64

// ---------------- scratch (device globals; no runtime allocation) ----------
__device__ __nv_bfloat16 g_Whi[(size_t)N_DIM * N_DIM];
__device__ __nv_bfloat16 g_Wlo[(size_t)N_DIM * N_DIM];
__device__ __nv_bfloat16 g_Xhi[(size_t)N_DIM * N_DIM];
__device__ __nv_bfloat16 g_Xlo[(size_t)N_DIM * N_DIM];

// ---------------- helpers ---------------------------------------------------
#define SMEM_SWIZZLE_128B(o) ((o) ^ (((o) >> 3) & 0x70))

__device__ __forceinline__ uint32_t smem_u32(const void* p) {
    uint32_t a;
    asm("{ .reg .u64 t; cvta.to.shared.u64 t, %1; cvt.u32.u64 %0, t; }"
        : "=r"(a) : "l"(p));
    return a;
}

__device__ __forceinline__ void cp_async16(uint32_t dst, const void* src) {
    asm volatile("cp.async.cg.shared.global [%0], [%1], 16;"
                 :: "r"(dst), "l"(src) : "memory");
}

__device__ __forceinline__ void ldm_x4(uint32_t (&r)[4], uint32_t addr) {
    asm volatile("ldmatrix.sync.aligned.m8n8.x4.shared.b16 {%0,%1,%2,%3}, [%4];"
                 : "=r"(r[0]), "=r"(r[1]), "=r"(r[2]), "=r"(r[3])
                 : "r"(addr));
}

__device__ __forceinline__ void mma_bf16(float (&d)[4], const uint32_t (&a)[4],
                                         uint32_t b0, uint32_t b1) {
    asm volatile(
        "mma.sync.aligned.m16n8k16.row.col.f32.bf16.bf16.f32 "
        "{%0,%1,%2,%3}, {%4,%5,%6,%7}, {%8,%9}, {%0,%1,%2,%3};"
        : "+f"(d[0]), "+f"(d[1]), "+f"(d[2]), "+f"(d[3])
        : "r"(a[0]), "r"(a[1]), "r"(a[2]), "r"(a[3]), "r"(b0), "r"(b1));
}

// ---------------- kernel 1: build W, split bf16 hi/lo (8 elems/thread) -----
__global__ __launch_bounds__(256) void build_w_kernel(
    const float* __restrict__ a0, const float* __restrict__ a1,
    const float* __restrict__ a2, const float* __restrict__ a3,
    const float* __restrict__ a4, const float* __restrict__ a5,
    const float* __restrict__ a6, const float* __restrict__ a7,
    const float* __restrict__ b0, const float* __restrict__ b1,
    const float* __restrict__ b2, const float* __restrict__ b3,
    const float* __restrict__ b4, const float* __restrict__ b5,
    const float* __restrict__ b6, const float* __restrict__ b7)
{
    const int t = blockIdx.x * blockDim.x + threadIdx.x;  // 0 .. 2.097M-1
    const int i  = t >> 9;          // row 0..4095
    const int j0 = (t & 511) << 3;  // 8-aligned col

    // a-values: constant across the 8-j block (all kron block sizes >= 8)
    const float av0 = a0[(i >> 6) * 64  + (j0 >> 6)];
    const float av1 = a1[(i >> 6) * 64  + (j0 >> 6)];
    const float av2 = a2[(i >> 7) * 32  + (j0 >> 7)];
    const float av3 = a3[(i >> 5) * 128 + (j0 >> 5)];
    const float av4 = a4[(i >> 8) * 16  + (j0 >> 8)];
    const float av5 = a5[(i >> 4) * 256 + (j0 >> 4)];
    const float av6 = a6[(i >> 9) * 8   + (j0 >> 9)];
    const float av7 = a7[(i >> 3) * 512 + (j0 >> 3)];

    // b-row pointers: contiguous 8 floats starting 32B-aligned
    const float4* p0 = reinterpret_cast<const float4*>(b0 + (i & 63)  * 64  + (j0 & 63));
    const float4* p1 = reinterpret_cast<const float4*>(b1 + (i & 63)  * 64  + (j0 & 63));
    const float4* p2 = reinterpret_cast<const float4*>(b2 + (i & 127) * 128 + (j0 & 127));
    const float4* p3 = reinterpret_cast<const float4*>(b3 + (i & 31)  * 32  + (j0 & 31));
    const float4* p4 = reinterpret_cast<const float4*>(b4 + (i & 255) * 256 + (j0 & 255));
    const float4* p5 = reinterpret_cast<const float4*>(b5 + (i & 15)  * 16  + (j0 & 15));
    const float4* p6 = reinterpret_cast<const float4*>(b6 + (i & 511) * 512 + (j0 & 511));
    const float4* p7 = reinterpret_cast<const float4*>(b7 + (i & 7)   * 8   + (j0 & 7));

    float s[8];
#pragma unroll
    for (int e = 0; e < 8; ++e) s[e] = 0.0f;

#pragma unroll
    for (int h = 0; h < 2; ++h) {
        float4 v0 = p0[h], v1 = p1[h], v2 = p2[h], v3 = p3[h];
        float4 v4 = p4[h], v5 = p5[h], v6 = p6[h], v7 = p7[h];
        float* e0 = &v0.x; float* e1 = &v1.x; float* e2 = &v2.x; float* e3 = &v3.x;
        float* e4 = &v4.x; float* e5 = &v5.x; float* e6 = &v6.x; float* e7 = &v7.x;
#pragma unroll
        for (int e = 0; e < 4; ++e) {
            float acc = av0 * e0[e];
            acc = fmaf(av1, e1[e], acc);
            acc = fmaf(av2, e2[e], acc);
            acc = fmaf(av3, e3[e], acc);
            acc = fmaf(av4, e4[e], acc);
            acc = fmaf(av5, e5[e], acc);
            acc = fmaf(av6, e6[e], acc);
            acc = fmaf(av7, e7[e], acc);
            s[h * 4 + e] = acc * 0.17677669529663687f;  // 1/(2*sqrt(8))
        }
    }

    __nv_bfloat16 hi8[8], lo8[8];
#pragma unroll
    for (int e = 0; e < 8; ++e) {
        __nv_bfloat16 hi = __float2bfloat16(s[e]);
        hi8[e] = hi;
        lo8[e] = __float2bfloat16(s[e] - __bfloat162float(hi));
    }
    const size_t o = (size_t)i * N_DIM + j0;
    *reinterpret_cast<uint4*>(g_Whi + o) = *reinterpret_cast<uint4*>(hi8);
    *reinterpret_cast<uint4*>(g_Wlo + o) = *reinterpret_cast<uint4*>(lo8);
}

// ---------------- kernel 2: split X into bf16 hi/lo ------------------------
__global__ __launch_bounds__(256) void split_x_kernel(const float* __restrict__ x)
{
    const int i = blockIdx.x * blockDim.x + threadIdx.x;  // float4 index
    float4 v = reinterpret_cast<const float4*>(x)[i];

    __nv_bfloat16 hx = __float2bfloat16(v.x);
    __nv_bfloat16 hy = __float2bfloat16(v.y);
    __nv_bfloat16 hz = __float2bfloat16(v.z);
    __nv_bfloat16 hw = __float2bfloat16(v.w);

    __nv_bfloat162 h0; h0.x = hx; h0.y = hy;
    __nv_bfloat162 h1; h1.x = hz; h1.y = hw;

    __nv_bfloat162 l0, l1;
    l0.x = __float2bfloat16(v.x - __bfloat162float(hx));
    l0.y = __float2bfloat16(v.y - __bfloat162float(hy));
    l1.x = __float2bfloat16(v.z - __bfloat162float(hz));
    l1.y = __float2bfloat16(v.w - __bfloat162float(hw));

    reinterpret_cast<__nv_bfloat162*>(g_Xhi)[2 * i]     = h0;
    reinterpret_cast<__nv_bfloat162*>(g_Xhi)[2 * i + 1] = h1;
    reinterpret_cast<__nv_bfloat162*>(g_Xlo)[2 * i]     = l0;
    reinterpret_cast<__nv_bfloat162*>(g_Xlo)[2 * i + 1] = l1;
}

// ---------------- kernel 3: mma.sync bf16-split GEMM ------------------------
// SMEM: 3 stages x 64KB:
//   +0      W_hi (128 x 64 bf16, SW128-swizzled 128B rows)
//   +16384  W_lo
//   +32768  X_hi
//   +49152  X_lo
static constexpr int SM_BUFSZ   = 65536;
static constexpr int NSTAGE     = 3;
static constexpr int SMEM_TOTAL = NSTAGE * SM_BUFSZ;  // 196608

__global__ __launch_bounds__(512, 1)
void gemm_kernel(const float* __restrict__ bias, float* __restrict__ out)
{
    extern __shared__ __align__(1024) char smem[];
    const uint32_t sb = smem_u32(smem);
    const int tid = threadIdx.x;
    const int wid = tid >> 5;
    const int lid = tid & 31;

    const int rbase = blockIdx.x * 128;  // M rows (W / OUTF)
    const int nbase = blockIdx.y * 128;  // N rows (X / BATCH)

    const int warp_m = wid & 3;   // 0..3 -> 32-row slab
    const int warp_n = wid >> 2;  // 0..3 -> 32-col slab

    const int lj   = lid & 7;   // row-within-8 for ldmatrix
    const int lsel = lid >> 3;  // which 8x8 matrix this lane feeds

    // ---- cp.async stage loader (512 threads, 8 cp.async each) -------------
    auto load_stage = [&](int t) {
        if (t < 64) {
            const uint32_t bufb = sb + (uint32_t)(t % NSTAGE) * SM_BUFSZ;
            const int k0 = t * KTILE;
#pragma unroll
            for (int s = 0; s < 2; ++s) {
                const int c    = tid + s * 512;  // 0..1023
                const int row  = c >> 3;         // 0..127
                const int ch   = c & 7;          // 16B chunk in row
                const uint32_t sw =
                    SMEM_SWIZZLE_128B((uint32_t)(row * 128 + ch * 16));
                const size_t gW = (size_t)(rbase + row) * N_DIM + k0 + ch * 8;
                const size_t gX = (size_t)(nbase + row) * N_DIM + k0 + ch * 8;
                cp_async16(bufb + sw,         g_Whi + gW);
                cp_async16(bufb + 16384 + sw, g_Wlo + gW);
                cp_async16(bufb + 32768 + sw, g_Xhi + gX);
                cp_async16(bufb + 49152 + sw, g_Xlo + gX);
            }
        }
        asm volatile("cp.async.commit_group;" ::: "memory");
    };

    // ---- accumulators: 2 m16-blocks x 4 n8-blocks x 4 regs -----------------
    float d[2][4][4];
#pragma unroll
    for (int mb = 0; mb < 2; ++mb)
#pragma unroll
        for (int q = 0; q < 4; ++q)
#pragma unroll
            for (int r = 0; r < 4; ++r) d[mb][q][r] = 0.0f;

    load_stage(0);
    load_stage(1);

    for (int t = 0; t < 64; ++t) {
        asm volatile("cp.async.wait_group 1;" ::: "memory");
        __syncthreads();

        load_stage(t + 2);

        const uint32_t bufb = sb + (uint32_t)(t % NSTAGE) * SM_BUFSZ;
        const uint32_t aHi = bufb;
        const uint32_t aLo = bufb + 16384;
        const uint32_t xHi = bufb + 32768;
        const uint32_t xLo = bufb + 49152;

#pragma unroll
        for (int ks = 0; ks < 4; ++ks) {
            const int kc = ks * 2;  // 16B-chunk index of this k16 step

            // A fragments (rows = M): x4 = (m0-7,k0),(m8-15,k0),(m0-7,k1),(m8-15,k1)
            uint32_t ah[2][4], al[2][4];
#pragma unroll
            for (int mb = 0; mb < 2; ++mb) {
                const int row = warp_m * 32 + mb * 16 + lj + ((lsel & 1) << 3);
                const int ch  = kc + (lsel >> 1);
                const uint32_t off =
                    SMEM_SWIZZLE_128B((uint32_t)(row * 128 + ch * 16));
                ldm_x4(ah[mb], aHi + off);
                ldm_x4(al[mb], aLo + off);
            }

            // B fragments (rows = N): x4 = (n0-7,k0),(n0-7,k1),(n8-15,k0),(n8-15,k1)
            uint32_t bh[2][4], bl[2][4];
#pragma unroll
            for (int nb = 0; nb < 2; ++nb) {
                const int row = warp_n * 32 + nb * 16 + lj + ((lsel >> 1) << 3);
                const int ch  = kc + (lsel & 1);
                const uint32_t off =
                    SMEM_SWIZZLE_128B((uint32_t)(row * 128 + ch * 16));
                ldm_x4(bh[nb], xHi + off);
                ldm_x4(bl[nb], xLo + off);
            }

            // 3-product split MMAs: 24 HMMA per ks
#pragma unroll
            for (int mb = 0; mb < 2; ++mb) {
#pragma unroll
                for (int nb = 0; nb < 2; ++nb) {
                    mma_bf16(d[mb][nb * 2 + 0], ah[mb], bh[nb][0], bh[nb][1]);
                    mma_bf16(d[mb][nb * 2 + 1], ah[mb], bh[nb][2], bh[nb][3]);
                    mma_bf16(d[mb][nb * 2 + 0], ah[mb], bl[nb][0], bl[nb][1]);
                    mma_bf16(d[mb][nb * 2 + 1], ah[mb], bl[nb][2], bl[nb][3]);
                    mma_bf16(d[mb][nb * 2 + 0], al[mb], bh[nb][0], bh[nb][1]);
                    mma_bf16(d[mb][nb * 2 + 1], al[mb], bh[nb][2], bh[nb][3]);
                }
            }
        }
    }

    asm volatile("cp.async.wait_group 0;" ::: "memory");

    // ---- epilogue: regs -> gmem (+bias) ------------------------------------
    // d-frag: d0,d1 -> row (lid>>2),   cols (lid&3)*2 + {0,1}
    //         d2,d3 -> row (lid>>2)+8, same cols
    const int rw = rbase + warp_m * 32 + (lid >> 2);
    const int cw = nbase + warp_n * 32 + (lid & 3) * 2;
#pragma unroll
    for (int mb = 0; mb < 2; ++mb) {
#pragma unroll
        for (int q = 0; q < 4; ++q) {
            const int col = cw + q * 8;
            const float b0 = __ldg(bias + col);
            const float b1 = __ldg(bias + col + 1);
            const int r0 = rw + mb * 16;
            float2 v0, v1;
            v0.x = d[mb][q][0] + b0;
            v0.y = d[mb][q][1] + b1;
            v1.x = d[mb][q][2] + b0;
            v1.y = d[mb][q][3] + b1;
            *reinterpret_cast<float2*>(out + (size_t)r0 * N_DIM + col) = v0;
            *reinterpret_cast<float2*>(out + (size_t)(r0 + 8) * N_DIM + col) = v1;
        }
    }
}

// ---------------- launch ----------------------------------------------------
extern "C" void kernel_launch(void* const* d_in, const int* in_sizes, int n_in,
                              void* d_out, int out_size)
{
    const float* x    = (const float*)d_in[0];
    const float* a[8] = {(const float*)d_in[1], (const float*)d_in[2],
                         (const float*)d_in[3], (const float*)d_in[4],
                         (const float*)d_in[5], (const float*)d_in[6],
                         (const float*)d_in[7], (const float*)d_in[8]};
    const float* b[8] = {(const float*)d_in[9],  (const float*)d_in[10],
                         (const float*)d_in[11], (const float*)d_in[12],
                         (const float*)d_in[13], (const float*)d_in[14],
                         (const float*)d_in[15], (const float*)d_in[16]};
    const float* bias = (const float*)d_in[17];
    float* out = (float*)d_out;

    cudaFuncSetAttribute(gemm_kernel,
                         cudaFuncAttributeMaxDynamicSharedMemorySize,
                         SMEM_TOTAL);

    // 1) W build + split: 8 outputs/thread
    build_w_kernel<<<(N_DIM * N_DIM / 8) / 256, 256>>>(
        a[0], a[1], a[2], a[3], a[4], a[5], a[6], a[7],
        b[0], b[1], b[2], b[3], b[4], b[5], b[6], b[7]);

    // 2) X split (float4-vectorized)
    split_x_kernel<<<(N_DIM * N_DIM / 4) / 256, 256>>>(x);

    // 3) GEMM: 32x32 grid of 128x128 tiles, 512 threads
    gemm_kernel<<<dim3(32, 32), 512, SMEM_TOTAL>>>(bias, out);
}

// round 9
// speedup vs baseline: 2.3774x; 2.3533x over previous
#include <cuda_runtime.h>
#include <cuda_bf16.h>
#include <cuda_fp16.h>
#include <cstdint>

// ============================================================================
// KLinear: y[i,n] = (sum_k kron(a_k,b_k)[i,j] / (2*sqrt(8))) * x[n,j] + bias[n]
//
// tcgen05 unavailable (harness PTX target = compute_103). GEMM uses base-PTX
// mma.sync.m16n8k16 fp16 + ldmatrix + cp.async.
//
// Precision plan (calibrated on round-7/8 measurements):
//   single-product fp16 GEMM, fp32 accumulation. Per-element fp16 quant rms
//   = 2^-11/sqrt(3) = 2.8e-4; product error = sqrt(2)*2.8e-4 = 4e-4 << 1e-3.
//
//   1) build W (fp32 math) -> fp16            (g_Wh)
//   2) convert X -> fp16                      (g_Xh)
//   3) fp16 GEMM: 128x128 CTA tile, 8 warps (4x2), 32x64 warp tile, KTILE=64,
//      SW128 swizzled smem, 4-stage cp.async pipeline (3 in flight).
// ============================================================================

#define N_DIM 4096
#define KTILE 64

// ---------------- scratch (device globals; no runtime allocation) ----------
__device__ __half g_Wh[(size_t)N_DIM * N_DIM];
__device__ __half g_Xh[(size_t)N_DIM * N_DIM];

// ---------------- helpers ---------------------------------------------------
#define SMEM_SWIZZLE_128B(o) ((o) ^ (((o) >> 3) & 0x70))

__device__ __forceinline__ uint32_t smem_u32(const void* p) {
    uint32_t a;
    asm("{ .reg .u64 t; cvta.to.shared.u64 t, %1; cvt.u32.u64 %0, t; }"
        : "=r"(a) : "l"(p));
    return a;
}

__device__ __forceinline__ void cp_async16(uint32_t dst, const void* src) {
    asm volatile("cp.async.cg.shared.global [%0], [%1], 16;"
                 :: "r"(dst), "l"(src) : "memory");
}

__device__ __forceinline__ void ldm_x4(uint32_t (&r)[4], uint32_t addr) {
    asm volatile("ldmatrix.sync.aligned.m8n8.x4.shared.b16 {%0,%1,%2,%3}, [%4];"
                 : "=r"(r[0]), "=r"(r[1]), "=r"(r[2]), "=r"(r[3])
                 : "r"(addr));
}

__device__ __forceinline__ void mma_fp16(float (&d)[4], const uint32_t (&a)[4],
                                         uint32_t b0, uint32_t b1) {
    asm volatile(
        "mma.sync.aligned.m16n8k16.row.col.f32.f16.f16.f32 "
        "{%0,%1,%2,%3}, {%4,%5,%6,%7}, {%8,%9}, {%0,%1,%2,%3};"
        : "+f"(d[0]), "+f"(d[1]), "+f"(d[2]), "+f"(d[3])
        : "r"(a[0]), "r"(a[1]), "r"(a[2]), "r"(a[3]), "r"(b0), "r"(b1));
}

// ---------------- kernel 1: build W in fp32, store fp16 (8 elems/thread) ---
__global__ __launch_bounds__(256) void build_w_kernel(
    const float* __restrict__ a0, const float* __restrict__ a1,
    const float* __restrict__ a2, const float* __restrict__ a3,
    const float* __restrict__ a4, const float* __restrict__ a5,
    const float* __restrict__ a6, const float* __restrict__ a7,
    const float* __restrict__ b0, const float* __restrict__ b1,
    const float* __restrict__ b2, const float* __restrict__ b3,
    const float* __restrict__ b4, const float* __restrict__ b5,
    const float* __restrict__ b6, const float* __restrict__ b7)
{
    const int t = blockIdx.x * blockDim.x + threadIdx.x;  // 0 .. 2.097M-1
    const int i  = t >> 9;          // row 0..4095
    const int j0 = (t & 511) << 3;  // 8-aligned col

    // a-values: constant across the 8-j block (all kron col-block sizes >= 8)
    const float av0 = a0[(i >> 6) * 64  + (j0 >> 6)];
    const float av1 = a1[(i >> 6) * 64  + (j0 >> 6)];
    const float av2 = a2[(i >> 7) * 32  + (j0 >> 7)];
    const float av3 = a3[(i >> 5) * 128 + (j0 >> 5)];
    const float av4 = a4[(i >> 8) * 16  + (j0 >> 8)];
    const float av5 = a5[(i >> 4) * 256 + (j0 >> 4)];
    const float av6 = a6[(i >> 9) * 8   + (j0 >> 9)];
    const float av7 = a7[(i >> 3) * 512 + (j0 >> 3)];

    // b-row pointers: contiguous 8 floats starting 32B-aligned
    const float4* p0 = reinterpret_cast<const float4*>(b0 + (i & 63)  * 64  + (j0 & 63));
    const float4* p1 = reinterpret_cast<const float4*>(b1 + (i & 63)  * 64  + (j0 & 63));
    const float4* p2 = reinterpret_cast<const float4*>(b2 + (i & 127) * 128 + (j0 & 127));
    const float4* p3 = reinterpret_cast<const float4*>(b3 + (i & 31)  * 32  + (j0 & 31));
    const float4* p4 = reinterpret_cast<const float4*>(b4 + (i & 255) * 256 + (j0 & 255));
    const float4* p5 = reinterpret_cast<const float4*>(b5 + (i & 15)  * 16  + (j0 & 15));
    const float4* p6 = reinterpret_cast<const float4*>(b6 + (i & 511) * 512 + (j0 & 511));
    const float4* p7 = reinterpret_cast<const float4*>(b7 + (i & 7)   * 8   + (j0 & 7));

    float s[8];
#pragma unroll
    for (int e = 0; e < 8; ++e) s[e] = 0.0f;

#pragma unroll
    for (int h = 0; h < 2; ++h) {
        float4 v0 = p0[h], v1 = p1[h], v2 = p2[h], v3 = p3[h];
        float4 v4 = p4[h], v5 = p5[h], v6 = p6[h], v7 = p7[h];
        float* e0 = &v0.x; float* e1 = &v1.x; float* e2 = &v2.x; float* e3 = &v3.x;
        float* e4 = &v4.x; float* e5 = &v5.x; float* e6 = &v6.x; float* e7 = &v7.x;
#pragma unroll
        for (int e = 0; e < 4; ++e) {
            float acc = av0 * e0[e];
            acc = fmaf(av1, e1[e], acc);
            acc = fmaf(av2, e2[e], acc);
            acc = fmaf(av3, e3[e], acc);
            acc = fmaf(av4, e4[e], acc);
            acc = fmaf(av5, e5[e], acc);
            acc = fmaf(av6, e6[e], acc);
            acc = fmaf(av7, e7[e], acc);
            s[h * 4 + e] = acc * 0.17677669529663687f;  // 1/(2*sqrt(8))
        }
    }

    __half h8[8];
#pragma unroll
    for (int e = 0; e < 8; ++e) h8[e] = __float2half_rn(s[e]);
    *reinterpret_cast<uint4*>(g_Wh + (size_t)i * N_DIM + j0) =
        *reinterpret_cast<uint4*>(h8);
}

// ---------------- kernel 2: convert X to fp16 -------------------------------
__global__ __launch_bounds__(256) void split_x_kernel(const float* __restrict__ x)
{
    const int i = blockIdx.x * blockDim.x + threadIdx.x;  // float4 index
    float4 v = reinterpret_cast<const float4*>(x)[i];
    __half2 h0 = __floats2half2_rn(v.x, v.y);
    __half2 h1 = __floats2half2_rn(v.z, v.w);
    reinterpret_cast<__half2*>(g_Xh)[2 * i]     = h0;
    reinterpret_cast<__half2*>(g_Xh)[2 * i + 1] = h1;
}

// ---------------- kernel 3: fp16 mma.sync GEMM ------------------------------
// SMEM: 4 stages x 32KB:
//   +0      W (128 x 64 fp16, SW128-swizzled 128B rows)
//   +16384  X
static constexpr int SM_BUFSZ   = 32768;
static constexpr int NSTAGE     = 4;
static constexpr int SMEM_TOTAL = NSTAGE * SM_BUFSZ;  // 131072

__global__ __launch_bounds__(256, 1)
void gemm_kernel(const float* __restrict__ bias, float* __restrict__ out)
{
    extern __shared__ __align__(1024) char smem[];
    const uint32_t sb = smem_u32(smem);
    const int tid = threadIdx.x;
    const int wid = tid >> 5;
    const int lid = tid & 31;

    const int rbase = blockIdx.x * 128;  // M rows (W / OUTF)
    const int nbase = blockIdx.y * 128;  // N rows (X / BATCH)

    const int warp_m = wid & 3;   // 0..3 -> 32-row slab
    const int warp_n = wid >> 2;  // 0..1 -> 64-col slab

    const int lj   = lid & 7;   // row-within-8 for ldmatrix
    const int lsel = lid >> 3;  // which 8x8 matrix this lane feeds

    // ---- cp.async stage loader: 2048 chunks of 16B, 8 per thread ----------
    auto load_stage = [&](int t) {
        if (t < 64) {
            const uint32_t bufb = sb + (uint32_t)(t % NSTAGE) * SM_BUFSZ;
            const int k0 = t * KTILE;
#pragma unroll
            for (int s = 0; s < 4; ++s) {
                const int c    = tid + s * 256;  // 0..1023
                const int row  = c >> 3;         // 0..127
                const int ch   = c & 7;          // 16B chunk in row
                const uint32_t sw =
                    SMEM_SWIZZLE_128B((uint32_t)(row * 128 + ch * 16));
                const size_t gW = (size_t)(rbase + row) * N_DIM + k0 + ch * 8;
                const size_t gX = (size_t)(nbase + row) * N_DIM + k0 + ch * 8;
                cp_async16(bufb + sw,         g_Wh + gW);
                cp_async16(bufb + 16384 + sw, g_Xh + gX);
            }
        }
        asm volatile("cp.async.commit_group;" ::: "memory");
    };

    // ---- accumulators: 2 m16-blocks x 8 n8-blocks x 4 regs -----------------
    float d[2][8][4];
#pragma unroll
    for (int mb = 0; mb < 2; ++mb)
#pragma unroll
        for (int q = 0; q < 8; ++q)
#pragma unroll
            for (int r = 0; r < 4; ++r) d[mb][q][r] = 0.0f;

    load_stage(0);
    load_stage(1);
    load_stage(2);

    for (int t = 0; t < 64; ++t) {
        // groups <= t complete (3 newest may be pending)
        asm volatile("cp.async.wait_group 2;" ::: "memory");
        __syncthreads();

        load_stage(t + 3);

        const uint32_t bufb = sb + (uint32_t)(t % NSTAGE) * SM_BUFSZ;
        const uint32_t aS = bufb;
        const uint32_t xS = bufb + 16384;

#pragma unroll
        for (int ks = 0; ks < 4; ++ks) {
            const int kc = ks * 2;  // 16B-chunk index of this k16 step

            // A fragments (rows = M): x4 = (m0-7,k0),(m8-15,k0),(m0-7,k1),(m8-15,k1)
            uint32_t ah[2][4];
#pragma unroll
            for (int mb = 0; mb < 2; ++mb) {
                const int row = warp_m * 32 + mb * 16 + lj + ((lsel & 1) << 3);
                const int ch  = kc + (lsel >> 1);
                const uint32_t off =
                    SMEM_SWIZZLE_128B((uint32_t)(row * 128 + ch * 16));
                ldm_x4(ah[mb], aS + off);
            }

            // B fragments (rows = N): x4 = (n0-7,k0),(n0-7,k1),(n8-15,k0),(n8-15,k1)
            uint32_t bh[4][4];
#pragma unroll
            for (int nb = 0; nb < 4; ++nb) {
                const int row = warp_n * 64 + nb * 16 + lj + ((lsel >> 1) << 3);
                const int ch  = kc + (lsel & 1);
                const uint32_t off =
                    SMEM_SWIZZLE_128B((uint32_t)(row * 128 + ch * 16));
                ldm_x4(bh[nb], xS + off);
            }

            // 16 HMMA per ks
#pragma unroll
            for (int mb = 0; mb < 2; ++mb) {
#pragma unroll
                for (int nb = 0; nb < 4; ++nb) {
                    mma_fp16(d[mb][nb * 2 + 0], ah[mb], bh[nb][0], bh[nb][1]);
                    mma_fp16(d[mb][nb * 2 + 1], ah[mb], bh[nb][2], bh[nb][3]);
                }
            }
        }
    }

    asm volatile("cp.async.wait_group 0;" ::: "memory");

    // ---- epilogue: regs -> gmem (+bias) ------------------------------------
    // d-frag: d0,d1 -> row (lid>>2),   cols (lid&3)*2 + {0,1}
    //         d2,d3 -> row (lid>>2)+8, same cols
    const int rw = rbase + warp_m * 32 + (lid >> 2);
    const int cw = nbase + warp_n * 64 + (lid & 3) * 2;
#pragma unroll
    for (int mb = 0; mb < 2; ++mb) {
#pragma unroll
        for (int q = 0; q < 8; ++q) {
            const int col = cw + q * 8;
            const float b0 = __ldg(bias + col);
            const float b1 = __ldg(bias + col + 1);
            const int r0 = rw + mb * 16;
            float2 v0, v1;
            v0.x = d[mb][q][0] + b0;
            v0.y = d[mb][q][1] + b1;
            v1.x = d[mb][q][2] + b0;
            v1.y = d[mb][q][3] + b1;
            *reinterpret_cast<float2*>(out + (size_t)r0 * N_DIM + col) = v0;
            *reinterpret_cast<float2*>(out + (size_t)(r0 + 8) * N_DIM + col) = v1;
        }
    }
}

// ---------------- launch ----------------------------------------------------
extern "C" void kernel_launch(void* const* d_in, const int* in_sizes, int n_in,
                              void* d_out, int out_size)
{
    const float* x    = (const float*)d_in[0];
    const float* a[8] = {(const float*)d_in[1], (const float*)d_in[2],
                         (const float*)d_in[3], (const float*)d_in[4],
                         (const float*)d_in[5], (const float*)d_in[6],
                         (const float*)d_in[7], (const float*)d_in[8]};
    const float* b[8] = {(const float*)d_in[9],  (const float*)d_in[10],
                         (const float*)d_in[11], (const float*)d_in[12],
                         (const float*)d_in[13], (const float*)d_in[14],
                         (const float*)d_in[15], (const float*)d_in[16]};
    const float* bias = (const float*)d_in[17];
    float* out = (float*)d_out;

    cudaFuncSetAttribute(gemm_kernel,
                         cudaFuncAttributeMaxDynamicSharedMemorySize,
                         SMEM_TOTAL);

    // 1) W build (fp32 math, fp16 store): 8 outputs/thread
    build_w_kernel<<<(N_DIM * N_DIM / 8) / 256, 256>>>(
        a[0], a[1], a[2], a[3], a[4], a[5], a[6], a[7],
        b[0], b[1], b[2], b[3], b[4], b[5], b[6], b[7]);

    // 2) X -> fp16
    split_x_kernel<<<(N_DIM * N_DIM / 4) / 256, 256>>>(x);

    // 3) GEMM: 32x32 grid of 128x128 tiles, 256 threads
    gemm_kernel<<<dim3(32, 32), 256, SMEM_TOTAL>>>(bias, out);
}

// round 10
// speedup vs baseline: 2.3988x; 1.0090x over previous
#include <cuda_runtime.h>
#include <cuda_bf16.h>
#include <cuda_fp16.h>
#include <cstdint>

// ============================================================================
// KLinear: y[i,n] = (sum_k kron(a_k,b_k)[i,j] / (2*sqrt(8))) * x[n,j] + bias[n]
//
// fp16 single-product GEMM (calibrated rel_err ~2.9e-4 < 1e-3), fp32 accum.
// Round-9 -> round-10 GEMM changes:
//   * CTA tile 256x128 (8 warps, 4Mx2N), warp tile 64x64
//     -> smem bytes/MAC 0.125 -> 0.084 (HMMA:LDSM 2.7 -> 4)
//   * fragment double-buffering across k16 steps (LDSM || HMMA)
//   * 4-stage cp.async pipeline, 48KB/stage (192KB smem)
// ============================================================================

#define N_DIM 4096

// ---------------- scratch (device globals; no runtime allocation) ----------
__device__ __half g_Wh[(size_t)N_DIM * N_DIM];
__device__ __half g_Xh[(size_t)N_DIM * N_DIM];

// ---------------- helpers ---------------------------------------------------
#define SMEM_SWIZZLE_128B(o) ((o) ^ (((o) >> 3) & 0x70))

__device__ __forceinline__ uint32_t smem_u32(const void* p) {
    uint32_t a;
    asm("{ .reg .u64 t; cvta.to.shared.u64 t, %1; cvt.u32.u64 %0, t; }"
        : "=r"(a) : "l"(p));
    return a;
}

__device__ __forceinline__ void cp_async16(uint32_t dst, const void* src) {
    asm volatile("cp.async.cg.shared.global [%0], [%1], 16;"
                 :: "r"(dst), "l"(src) : "memory");
}

__device__ __forceinline__ void ldm_x4(uint32_t (&r)[4], uint32_t addr) {
    asm volatile("ldmatrix.sync.aligned.m8n8.x4.shared.b16 {%0,%1,%2,%3}, [%4];"
                 : "=r"(r[0]), "=r"(r[1]), "=r"(r[2]), "=r"(r[3])
                 : "r"(addr));
}

__device__ __forceinline__ void mma_fp16(float (&d)[4], const uint32_t (&a)[4],
                                         uint32_t b0, uint32_t b1) {
    asm volatile(
        "mma.sync.aligned.m16n8k16.row.col.f32.f16.f16.f32 "
        "{%0,%1,%2,%3}, {%4,%5,%6,%7}, {%8,%9}, {%0,%1,%2,%3};"
        : "+f"(d[0]), "+f"(d[1]), "+f"(d[2]), "+f"(d[3])
        : "r"(a[0]), "r"(a[1]), "r"(a[2]), "r"(a[3]), "r"(b0), "r"(b1));
}

// ---------------- kernel 1: build W in fp32, store fp16 (8 elems/thread) ---
__global__ __launch_bounds__(256) void build_w_kernel(
    const float* __restrict__ a0, const float* __restrict__ a1,
    const float* __restrict__ a2, const float* __restrict__ a3,
    const float* __restrict__ a4, const float* __restrict__ a5,
    const float* __restrict__ a6, const float* __restrict__ a7,
    const float* __restrict__ b0, const float* __restrict__ b1,
    const float* __restrict__ b2, const float* __restrict__ b3,
    const float* __restrict__ b4, const float* __restrict__ b5,
    const float* __restrict__ b6, const float* __restrict__ b7)
{
    const int t = blockIdx.x * blockDim.x + threadIdx.x;  // 0 .. 2.097M-1
    const int i  = t >> 9;          // row 0..4095
    const int j0 = (t & 511) << 3;  // 8-aligned col

    const float av0 = a0[(i >> 6) * 64  + (j0 >> 6)];
    const float av1 = a1[(i >> 6) * 64  + (j0 >> 6)];
    const float av2 = a2[(i >> 7) * 32  + (j0 >> 7)];
    const float av3 = a3[(i >> 5) * 128 + (j0 >> 5)];
    const float av4 = a4[(i >> 8) * 16  + (j0 >> 8)];
    const float av5 = a5[(i >> 4) * 256 + (j0 >> 4)];
    const float av6 = a6[(i >> 9) * 8   + (j0 >> 9)];
    const float av7 = a7[(i >> 3) * 512 + (j0 >> 3)];

    const float4* p0 = reinterpret_cast<const float4*>(b0 + (i & 63)  * 64  + (j0 & 63));
    const float4* p1 = reinterpret_cast<const float4*>(b1 + (i & 63)  * 64  + (j0 & 63));
    const float4* p2 = reinterpret_cast<const float4*>(b2 + (i & 127) * 128 + (j0 & 127));
    const float4* p3 = reinterpret_cast<const float4*>(b3 + (i & 31)  * 32  + (j0 & 31));
    const float4* p4 = reinterpret_cast<const float4*>(b4 + (i & 255) * 256 + (j0 & 255));
    const float4* p5 = reinterpret_cast<const float4*>(b5 + (i & 15)  * 16  + (j0 & 15));
    const float4* p6 = reinterpret_cast<const float4*>(b6 + (i & 511) * 512 + (j0 & 511));
    const float4* p7 = reinterpret_cast<const float4*>(b7 + (i & 7)   * 8   + (j0 & 7));

    float s[8];
#pragma unroll
    for (int e = 0; e < 8; ++e) s[e] = 0.0f;

#pragma unroll
    for (int h = 0; h < 2; ++h) {
        float4 v0 = p0[h], v1 = p1[h], v2 = p2[h], v3 = p3[h];
        float4 v4 = p4[h], v5 = p5[h], v6 = p6[h], v7 = p7[h];
        float* e0 = &v0.x; float* e1 = &v1.x; float* e2 = &v2.x; float* e3 = &v3.x;
        float* e4 = &v4.x; float* e5 = &v5.x; float* e6 = &v6.x; float* e7 = &v7.x;
#pragma unroll
        for (int e = 0; e < 4; ++e) {
            float acc = av0 * e0[e];
            acc = fmaf(av1, e1[e], acc);
            acc = fmaf(av2, e2[e], acc);
            acc = fmaf(av3, e3[e], acc);
            acc = fmaf(av4, e4[e], acc);
            acc = fmaf(av5, e5[e], acc);
            acc = fmaf(av6, e6[e], acc);
            acc = fmaf(av7, e7[e], acc);
            s[h * 4 + e] = acc * 0.17677669529663687f;  // 1/(2*sqrt(8))
        }
    }

    __half h8[8];
#pragma unroll
    for (int e = 0; e < 8; ++e) h8[e] = __float2half_rn(s[e]);
    *reinterpret_cast<uint4*>(g_Wh + (size_t)i * N_DIM + j0) =
        *reinterpret_cast<uint4*>(h8);
}

// ---------------- kernel 2: convert X to fp16 -------------------------------
__global__ __launch_bounds__(256) void split_x_kernel(const float* __restrict__ x)
{
    const int i = blockIdx.x * blockDim.x + threadIdx.x;  // float4 index
    float4 v = reinterpret_cast<const float4*>(x)[i];
    __half2 h0 = __floats2half2_rn(v.x, v.y);
    __half2 h1 = __floats2half2_rn(v.z, v.w);
    reinterpret_cast<__half2*>(g_Xh)[2 * i]     = h0;
    reinterpret_cast<__half2*>(g_Xh)[2 * i + 1] = h1;
}

// ---------------- kernel 3: fp16 mma.sync GEMM ------------------------------
// CTA tile 256(M) x 128(N), KTILE=64. SMEM: 4 stages x 48KB:
//   +0      W (256 x 64 fp16, SW128-swizzled 128B rows)  = 32KB
//   +32768  X (128 x 64 fp16)                            = 16KB
static constexpr int SM_BUFSZ   = 49152;
static constexpr int NSTAGE     = 4;
static constexpr int SMEM_TOTAL = NSTAGE * SM_BUFSZ;  // 196608

__global__ __launch_bounds__(256, 1)
void gemm_kernel(const float* __restrict__ bias, float* __restrict__ out)
{
    extern __shared__ __align__(1024) char smem[];
    const uint32_t sb = smem_u32(smem);
    const int tid = threadIdx.x;
    const int wid = tid >> 5;
    const int lid = tid & 31;

    const int rbase = blockIdx.x * 256;  // M rows (W / OUTF)
    const int nbase = blockIdx.y * 128;  // N rows (X / BATCH)

    const int warp_m = wid & 3;   // 0..3 -> 64-row slab
    const int warp_n = wid >> 2;  // 0..1 -> 64-col slab

    const int lj   = lid & 7;   // row-within-8 for ldmatrix
    const int lsel = lid >> 3;  // which 8x8 matrix this lane feeds

    // ---- cp.async stage loader: 3072 chunks of 16B, 12 per thread ---------
    auto load_stage = [&](int t) {
        if (t < 64) {
            const uint32_t bufb = sb + (uint32_t)(t & 3) * SM_BUFSZ;
            const int k0 = t * 64;
#pragma unroll
            for (int s = 0; s < 8; ++s) {        // W: 2048 chunks (256 rows)
                const int c   = tid + s * 256;
                const int row = c >> 3;
                const int ch  = c & 7;
                const uint32_t sw =
                    SMEM_SWIZZLE_128B((uint32_t)(row * 128 + ch * 16));
                cp_async16(bufb + sw,
                           g_Wh + (size_t)(rbase + row) * N_DIM + k0 + ch * 8);
            }
#pragma unroll
            for (int s = 0; s < 4; ++s) {        // X: 1024 chunks (128 rows)
                const int c   = tid + s * 256;
                const int row = c >> 3;
                const int ch  = c & 7;
                const uint32_t sw =
                    SMEM_SWIZZLE_128B((uint32_t)(row * 128 + ch * 16));
                cp_async16(bufb + 32768 + sw,
                           g_Xh + (size_t)(nbase + row) * N_DIM + k0 + ch * 8);
            }
        }
        asm volatile("cp.async.commit_group;" ::: "memory");
    };

    // fragment loader for one k16 step from stage base
    auto load_frags = [&](uint32_t bufb, int ks,
                          uint32_t (&A)[4][4], uint32_t (&B)[4][4]) {
        const int kc = ks * 2;
#pragma unroll
        for (int mb = 0; mb < 4; ++mb) {
            const int row = warp_m * 64 + mb * 16 + lj + ((lsel & 1) << 3);
            const int ch  = kc + (lsel >> 1);
            ldm_x4(A[mb], bufb +
                   SMEM_SWIZZLE_128B((uint32_t)(row * 128 + ch * 16)));
        }
#pragma unroll
        for (int nb = 0; nb < 4; ++nb) {
            const int row = warp_n * 64 + nb * 16 + lj + ((lsel >> 1) << 3);
            const int ch  = kc + (lsel & 1);
            ldm_x4(B[nb], bufb + 32768 +
                   SMEM_SWIZZLE_128B((uint32_t)(row * 128 + ch * 16)));
        }
    };

    // ---- accumulators: 4 m16-blocks x 8 n8-blocks x 4 regs = 128 ----------
    float d[4][8][4];
#pragma unroll
    for (int mb = 0; mb < 4; ++mb)
#pragma unroll
        for (int q = 0; q < 8; ++q)
#pragma unroll
            for (int r = 0; r < 4; ++r) d[mb][q][r] = 0.0f;

    load_stage(0);
    load_stage(1);
    load_stage(2);

    uint32_t fA[2][4][4], fB[2][4][4];

    for (int t = 0; t < 64; ++t) {
        // stage t resident (<=2 newest groups pending)
        asm volatile("cp.async.wait_group 2;" ::: "memory");
        __syncthreads();

        load_stage(t + 3);

        const uint32_t bufb = sb + (uint32_t)(t & 3) * SM_BUFSZ;

        load_frags(bufb, 0, fA[0], fB[0]);

#pragma unroll
        for (int ks = 0; ks < 4; ++ks) {
            const int cur = ks & 1;
            if (ks < 3) load_frags(bufb, ks + 1, fA[cur ^ 1], fB[cur ^ 1]);

            // 32 HMMA on the current fragment buffer
#pragma unroll
            for (int mb = 0; mb < 4; ++mb) {
#pragma unroll
                for (int nb = 0; nb < 4; ++nb) {
                    mma_fp16(d[mb][nb * 2 + 0], fA[cur][mb],
                             fB[cur][nb][0], fB[cur][nb][1]);
                    mma_fp16(d[mb][nb * 2 + 1], fA[cur][mb],
                             fB[cur][nb][2], fB[cur][nb][3]);
                }
            }
        }
    }

    asm volatile("cp.async.wait_group 0;" ::: "memory");

    // ---- epilogue: regs -> gmem (+bias) ------------------------------------
    // d-frag: d0,d1 -> row (lid>>2),   cols (lid&3)*2 + {0,1}
    //         d2,d3 -> row (lid>>2)+8, same cols
    const int rw = rbase + warp_m * 64 + (lid >> 2);
    const int cw = nbase + warp_n * 64 + (lid & 3) * 2;
#pragma unroll
    for (int mb = 0; mb < 4; ++mb) {
#pragma unroll
        for (int q = 0; q < 8; ++q) {
            const int col = cw + q * 8;
            const float b0 = __ldg(bias + col);
            const float b1 = __ldg(bias + col + 1);
            const int r0 = rw + mb * 16;
            float2 v0, v1;
            v0.x = d[mb][q][0] + b0;
            v0.y = d[mb][q][1] + b1;
            v1.x = d[mb][q][2] + b0;
            v1.y = d[mb][q][3] + b1;
            *reinterpret_cast<float2*>(out + (size_t)r0 * N_DIM + col) = v0;
            *reinterpret_cast<float2*>(out + (size_t)(r0 + 8) * N_DIM + col) = v1;
        }
    }
}

// ---------------- launch ----------------------------------------------------
extern "C" void kernel_launch(void* const* d_in, const int* in_sizes, int n_in,
                              void* d_out, int out_size)
{
    const float* x    = (const float*)d_in[0];
    const float* a[8] = {(const float*)d_in[1], (const float*)d_in[2],
                         (const float*)d_in[3], (const float*)d_in[4],
                         (const float*)d_in[5], (const float*)d_in[6],
                         (const float*)d_in[7], (const float*)d_in[8]};
    const float* b[8] = {(const float*)d_in[9],  (const float*)d_in[10],
                         (const float*)d_in[11], (const float*)d_in[12],
                         (const float*)d_in[13], (const float*)d_in[14],
                         (const float*)d_in[15], (const float*)d_in[16]};
    const float* bias = (const float*)d_in[17];
    float* out = (float*)d_out;

    cudaFuncSetAttribute(gemm_kernel,
                         cudaFuncAttributeMaxDynamicSharedMemorySize,
                         SMEM_TOTAL);

    // 1) W build (fp32 math, fp16 store): 8 outputs/thread
    build_w_kernel<<<(N_DIM * N_DIM / 8) / 256, 256>>>(
        a[0], a[1], a[2], a[3], a[4], a[5], a[6], a[7],
        b[0], b[1], b[2], b[3], b[4], b[5], b[6], b[7]);

    // 2) X -> fp16
    split_x_kernel<<<(N_DIM * N_DIM / 4) / 256, 256>>>(x);

    // 3) GEMM: 16x32 grid of 256x128 tiles, 256 threads
    gemm_kernel<<<dim3(16, 32), 256, SMEM_TOTAL>>>(bias, out);
}

// round 11
// speedup vs baseline: 2.4478x; 1.0204x over previous
#include <cuda_runtime.h>
#include <cuda_bf16.h>
#include <cuda_fp16.h>
#include <cstdint>

// ============================================================================
// KLinear: y[i,n] = (sum_k kron(a_k,b_k)[i,j] / (2*sqrt(8))) * x[n,j] + bias[n]
//
// fp16 single-product GEMM (calibrated rel_err 2.93e-4 < 1e-3), fp32 accum.
// Round-11 GEMM: 512 threads (16 warps -> 4 warps/SMSP; R8-vs-R9 contrast
// showed per-HMMA cost tracks warps/SMSP: 10.2 vs 12.9 cyc). CTA 256x128,
// warp tile 64x32, KTILE=64, 4-stage x 48KB cp.async pipeline.
// ============================================================================

#define N_DIM 4096

// ---------------- scratch (device globals; no runtime allocation) ----------
__device__ __half g_Wh[(size_t)N_DIM * N_DIM];
__device__ __half g_Xh[(size_t)N_DIM * N_DIM];

// ---------------- helpers ---------------------------------------------------
#define SMEM_SWIZZLE_128B(o) ((o) ^ (((o) >> 3) & 0x70))

__device__ __forceinline__ uint32_t smem_u32(const void* p) {
    uint32_t a;
    asm("{ .reg .u64 t; cvta.to.shared.u64 t, %1; cvt.u32.u64 %0, t; }"
        : "=r"(a) : "l"(p));
    return a;
}

__device__ __forceinline__ void cp_async16(uint32_t dst, const void* src) {
    asm volatile("cp.async.cg.shared.global [%0], [%1], 16;"
                 :: "r"(dst), "l"(src) : "memory");
}

__device__ __forceinline__ void ldm_x4(uint32_t (&r)[4], uint32_t addr) {
    asm volatile("ldmatrix.sync.aligned.m8n8.x4.shared.b16 {%0,%1,%2,%3}, [%4];"
                 : "=r"(r[0]), "=r"(r[1]), "=r"(r[2]), "=r"(r[3])
                 : "r"(addr));
}

__device__ __forceinline__ void mma_fp16(float (&d)[4], const uint32_t (&a)[4],
                                         uint32_t b0, uint32_t b1) {
    asm volatile(
        "mma.sync.aligned.m16n8k16.row.col.f32.f16.f16.f32 "
        "{%0,%1,%2,%3}, {%4,%5,%6,%7}, {%8,%9}, {%0,%1,%2,%3};"
        : "+f"(d[0]), "+f"(d[1]), "+f"(d[2]), "+f"(d[3])
        : "r"(a[0]), "r"(a[1]), "r"(a[2]), "r"(a[3]), "r"(b0), "r"(b1));
}

// ---------------- kernel 1: build W in fp32, store fp16 (8 elems/thread) ---
__global__ __launch_bounds__(256) void build_w_kernel(
    const float* __restrict__ a0, const float* __restrict__ a1,
    const float* __restrict__ a2, const float* __restrict__ a3,
    const float* __restrict__ a4, const float* __restrict__ a5,
    const float* __restrict__ a6, const float* __restrict__ a7,
    const float* __restrict__ b0, const float* __restrict__ b1,
    const float* __restrict__ b2, const float* __restrict__ b3,
    const float* __restrict__ b4, const float* __restrict__ b5,
    const float* __restrict__ b6, const float* __restrict__ b7)
{
    const int t = blockIdx.x * blockDim.x + threadIdx.x;  // 0 .. 2.097M-1
    const int i  = t >> 9;          // row 0..4095
    const int j0 = (t & 511) << 3;  // 8-aligned col

    const float av0 = a0[(i >> 6) * 64  + (j0 >> 6)];
    const float av1 = a1[(i >> 6) * 64  + (j0 >> 6)];
    const float av2 = a2[(i >> 7) * 32  + (j0 >> 7)];
    const float av3 = a3[(i >> 5) * 128 + (j0 >> 5)];
    const float av4 = a4[(i >> 8) * 16  + (j0 >> 8)];
    const float av5 = a5[(i >> 4) * 256 + (j0 >> 4)];
    const float av6 = a6[(i >> 9) * 8   + (j0 >> 9)];
    const float av7 = a7[(i >> 3) * 512 + (j0 >> 3)];

    const float4* p0 = reinterpret_cast<const float4*>(b0 + (i & 63)  * 64  + (j0 & 63));
    const float4* p1 = reinterpret_cast<const float4*>(b1 + (i & 63)  * 64  + (j0 & 63));
    const float4* p2 = reinterpret_cast<const float4*>(b2 + (i & 127) * 128 + (j0 & 127));
    const float4* p3 = reinterpret_cast<const float4*>(b3 + (i & 31)  * 32  + (j0 & 31));
    const float4* p4 = reinterpret_cast<const float4*>(b4 + (i & 255) * 256 + (j0 & 255));
    const float4* p5 = reinterpret_cast<const float4*>(b5 + (i & 15)  * 16  + (j0 & 15));
    const float4* p6 = reinterpret_cast<const float4*>(b6 + (i & 511) * 512 + (j0 & 511));
    const float4* p7 = reinterpret_cast<const float4*>(b7 + (i & 7)   * 8   + (j0 & 7));

    float s[8];
#pragma unroll
    for (int e = 0; e < 8; ++e) s[e] = 0.0f;

#pragma unroll
    for (int h = 0; h < 2; ++h) {
        float4 v0 = p0[h], v1 = p1[h], v2 = p2[h], v3 = p3[h];
        float4 v4 = p4[h], v5 = p5[h], v6 = p6[h], v7 = p7[h];
        float* e0 = &v0.x; float* e1 = &v1.x; float* e2 = &v2.x; float* e3 = &v3.x;
        float* e4 = &v4.x; float* e5 = &v5.x; float* e6 = &v6.x; float* e7 = &v7.x;
#pragma unroll
        for (int e = 0; e < 4; ++e) {
            float acc = av0 * e0[e];
            acc = fmaf(av1, e1[e], acc);
            acc = fmaf(av2, e2[e], acc);
            acc = fmaf(av3, e3[e], acc);
            acc = fmaf(av4, e4[e], acc);
            acc = fmaf(av5, e5[e], acc);
            acc = fmaf(av6, e6[e], acc);
            acc = fmaf(av7, e7[e], acc);
            s[h * 4 + e] = acc * 0.17677669529663687f;  // 1/(2*sqrt(8))
        }
    }

    __half h8[8];
#pragma unroll
    for (int e = 0; e < 8; ++e) h8[e] = __float2half_rn(s[e]);
    *reinterpret_cast<uint4*>(g_Wh + (size_t)i * N_DIM + j0) =
        *reinterpret_cast<uint4*>(h8);
}

// ---------------- kernel 2: convert X to fp16 -------------------------------
__global__ __launch_bounds__(256) void split_x_kernel(const float* __restrict__ x)
{
    const int i = blockIdx.x * blockDim.x + threadIdx.x;  // float4 index
    float4 v = reinterpret_cast<const float4*>(x)[i];
    __half2 h0 = __floats2half2_rn(v.x, v.y);
    __half2 h1 = __floats2half2_rn(v.z, v.w);
    reinterpret_cast<__half2*>(g_Xh)[2 * i]     = h0;
    reinterpret_cast<__half2*>(g_Xh)[2 * i + 1] = h1;
}

// ---------------- kernel 3: fp16 mma.sync GEMM ------------------------------
// CTA tile 256(M) x 128(N), KTILE=64, 512 threads (16 warps: 4M x 4N).
// SMEM: 4 stages x 48KB:
//   +0      W (256 x 64 fp16, SW128-swizzled 128B rows)  = 32KB
//   +32768  X (128 x 64 fp16)                            = 16KB
static constexpr int SM_BUFSZ   = 49152;
static constexpr int NSTAGE     = 4;
static constexpr int SMEM_TOTAL = NSTAGE * SM_BUFSZ;  // 196608

__global__ __launch_bounds__(512, 1)
void gemm_kernel(const float* __restrict__ bias, float* __restrict__ out)
{
    extern __shared__ __align__(1024) char smem[];
    const uint32_t sb = smem_u32(smem);
    const int tid = threadIdx.x;
    const int wid = tid >> 5;
    const int lid = tid & 31;

    const int rbase = blockIdx.x * 256;  // M rows (W / OUTF)
    const int nbase = blockIdx.y * 128;  // N rows (X / BATCH)

    const int warp_m = wid & 3;   // 0..3 -> 64-row slab
    const int warp_n = wid >> 2;  // 0..3 -> 32-col slab

    const int lj   = lid & 7;   // row-within-8 for ldmatrix
    const int lsel = lid >> 3;  // which 8x8 matrix this lane feeds

    // ---- cp.async stage loader: 3072 chunks of 16B, 6 per thread ----------
    auto load_stage = [&](int t) {
        if (t < 64) {
            const uint32_t bufb = sb + (uint32_t)(t & 3) * SM_BUFSZ;
            const int k0 = t * 64;
#pragma unroll
            for (int s = 0; s < 4; ++s) {        // W: 2048 chunks (256 rows)
                const int c   = tid + s * 512;
                const int row = c >> 3;
                const int ch  = c & 7;
                const uint32_t sw =
                    SMEM_SWIZZLE_128B((uint32_t)(row * 128 + ch * 16));
                cp_async16(bufb + sw,
                           g_Wh + (size_t)(rbase + row) * N_DIM + k0 + ch * 8);
            }
#pragma unroll
            for (int s = 0; s < 2; ++s) {        // X: 1024 chunks (128 rows)
                const int c   = tid + s * 512;
                const int row = c >> 3;
                const int ch  = c & 7;
                const uint32_t sw =
                    SMEM_SWIZZLE_128B((uint32_t)(row * 128 + ch * 16));
                cp_async16(bufb + 32768 + sw,
                           g_Xh + (size_t)(nbase + row) * N_DIM + k0 + ch * 8);
            }
        }
        asm volatile("cp.async.commit_group;" ::: "memory");
    };

    // ---- accumulators: 4 m16-blocks x 4 n8-blocks x 4 regs = 64 -----------
    float d[4][4][4];
#pragma unroll
    for (int mb = 0; mb < 4; ++mb)
#pragma unroll
        for (int q = 0; q < 4; ++q)
#pragma unroll
            for (int r = 0; r < 4; ++r) d[mb][q][r] = 0.0f;

    load_stage(0);
    load_stage(1);
    load_stage(2);

    for (int t = 0; t < 64; ++t) {
        // stage t resident (<=2 newest groups pending)
        asm volatile("cp.async.wait_group 2;" ::: "memory");
        __syncthreads();

        load_stage(t + 3);

        const uint32_t bufb = sb + (uint32_t)(t & 3) * SM_BUFSZ;

#pragma unroll
        for (int ks = 0; ks < 4; ++ks) {
            const int kc = ks * 2;  // 16B-chunk index of this k16 step

            // A fragments (rows = M): 4 x m16
            uint32_t fA[4][4];
#pragma unroll
            for (int mb = 0; mb < 4; ++mb) {
                const int row = warp_m * 64 + mb * 16 + lj + ((lsel & 1) << 3);
                const int ch  = kc + (lsel >> 1);
                ldm_x4(fA[mb], bufb +
                       SMEM_SWIZZLE_128B((uint32_t)(row * 128 + ch * 16)));
            }

            // B fragments (rows = N): 2 x n16
            uint32_t fB[2][4];
#pragma unroll
            for (int nb = 0; nb < 2; ++nb) {
                const int row = warp_n * 32 + nb * 16 + lj + ((lsel >> 1) << 3);
                const int ch  = kc + (lsel & 1);
                ldm_x4(fB[nb], bufb + 32768 +
                       SMEM_SWIZZLE_128B((uint32_t)(row * 128 + ch * 16)));
            }

            // 16 HMMA per ks
#pragma unroll
            for (int mb = 0; mb < 4; ++mb) {
#pragma unroll
                for (int nb = 0; nb < 2; ++nb) {
                    mma_fp16(d[mb][nb * 2 + 0], fA[mb], fB[nb][0], fB[nb][1]);
                    mma_fp16(d[mb][nb * 2 + 1], fA[mb], fB[nb][2], fB[nb][3]);
                }
            }
        }
    }

    asm volatile("cp.async.wait_group 0;" ::: "memory");

    // ---- epilogue: regs -> gmem (+bias) ------------------------------------
    // d-frag: d0,d1 -> row (lid>>2),   cols (lid&3)*2 + {0,1}
    //         d2,d3 -> row (lid>>2)+8, same cols
    const int rw = rbase + warp_m * 64 + (lid >> 2);
    const int cw = nbase + warp_n * 32 + (lid & 3) * 2;
#pragma unroll
    for (int mb = 0; mb < 4; ++mb) {
#pragma unroll
        for (int q = 0; q < 4; ++q) {
            const int col = cw + q * 8;
            const float b0 = __ldg(bias + col);
            const float b1 = __ldg(bias + col + 1);
            const int r0 = rw + mb * 16;
            float2 v0, v1;
            v0.x = d[mb][q][0] + b0;
            v0.y = d[mb][q][1] + b1;
            v1.x = d[mb][q][2] + b0;
            v1.y = d[mb][q][3] + b1;
            *reinterpret_cast<float2*>(out + (size_t)r0 * N_DIM + col) = v0;
            *reinterpret_cast<float2*>(out + (size_t)(r0 + 8) * N_DIM + col) = v1;
        }
    }
}

// ---------------- launch ----------------------------------------------------
extern "C" void kernel_launch(void* const* d_in, const int* in_sizes, int n_in,
                              void* d_out, int out_size)
{
    const float* x    = (const float*)d_in[0];
    const float* a[8] = {(const float*)d_in[1], (const float*)d_in[2],
                         (const float*)d_in[3], (const float*)d_in[4],
                         (const float*)d_in[5], (const float*)d_in[6],
                         (const float*)d_in[7], (const float*)d_in[8]};
    const float* b[8] = {(const float*)d_in[9],  (const float*)d_in[10],
                         (const float*)d_in[11], (const float*)d_in[12],
                         (const float*)d_in[13], (const float*)d_in[14],
                         (const float*)d_in[15], (const float*)d_in[16]};
    const float* bias = (const float*)d_in[17];
    float* out = (float*)d_out;

    cudaFuncSetAttribute(gemm_kernel,
                         cudaFuncAttributeMaxDynamicSharedMemorySize,
                         SMEM_TOTAL);

    // 1) W build (fp32 math, fp16 store): 8 outputs/thread
    build_w_kernel<<<(N_DIM * N_DIM / 8) / 256, 256>>>(
        a[0], a[1], a[2], a[3], a[4], a[5], a[6], a[7],
        b[0], b[1], b[2], b[3], b[4], b[5], b[6], b[7]);

    // 2) X -> fp16
    split_x_kernel<<<(N_DIM * N_DIM / 4) / 256, 256>>>(x);

    // 3) GEMM: 16x32 grid of 256x128 tiles, 512 threads
    gemm_kernel<<<dim3(16, 32), 512, SMEM_TOTAL>>>(bias, out);
}

// round 12
// speedup vs baseline: 2.4849x; 1.0152x over previous
#include <cuda_runtime.h>
#include <cuda_bf16.h>
#include <cuda_fp16.h>
#include <cstdint>

// ============================================================================
// KLinear: y[i,n] = (sum_k kron(a_k,b_k)[i,j] / (2*sqrt(8))) * x[n,j] + bias[n]
//
// fp16 single-product GEMM (calibrated rel_err 2.93e-4), fp32 accum.
// Round-12: K-split 2 to kill wave quantization (512 CTAs / 148 SMs = 3.46
// waves -> 15.6% loss measured across R8/R11; 1024 CTAs = 6.92 -> 1.2%).
//   * init kernel pre-fills out with bias
//   * each GEMM CTA computes a 256x128 tile over half of K (2048) and
//     accumulates into out via red.global.add.v2.f32
// ============================================================================

#define N_DIM 4096

// ---------------- scratch (device globals; no runtime allocation) ----------
__device__ __half g_Wh[(size_t)N_DIM * N_DIM];
__device__ __half g_Xh[(size_t)N_DIM * N_DIM];

// ---------------- helpers ---------------------------------------------------
#define SMEM_SWIZZLE_128B(o) ((o) ^ (((o) >> 3) & 0x70))

__device__ __forceinline__ uint32_t smem_u32(const void* p) {
    uint32_t a;
    asm("{ .reg .u64 t; cvta.to.shared.u64 t, %1; cvt.u32.u64 %0, t; }"
        : "=r"(a) : "l"(p));
    return a;
}

__device__ __forceinline__ void cp_async16(uint32_t dst, const void* src) {
    asm volatile("cp.async.cg.shared.global [%0], [%1], 16;"
                 :: "r"(dst), "l"(src) : "memory");
}

__device__ __forceinline__ void ldm_x4(uint32_t (&r)[4], uint32_t addr) {
    asm volatile("ldmatrix.sync.aligned.m8n8.x4.shared.b16 {%0,%1,%2,%3}, [%4];"
                 : "=r"(r[0]), "=r"(r[1]), "=r"(r[2]), "=r"(r[3])
                 : "r"(addr));
}

__device__ __forceinline__ void mma_fp16(float (&d)[4], const uint32_t (&a)[4],
                                         uint32_t b0, uint32_t b1) {
    asm volatile(
        "mma.sync.aligned.m16n8k16.row.col.f32.f16.f16.f32 "
        "{%0,%1,%2,%3}, {%4,%5,%6,%7}, {%8,%9}, {%0,%1,%2,%3};"
        : "+f"(d[0]), "+f"(d[1]), "+f"(d[2]), "+f"(d[3])
        : "r"(a[0]), "r"(a[1]), "r"(a[2]), "r"(a[3]), "r"(b0), "r"(b1));
}

__device__ __forceinline__ void red_add_v2(float* ptr, float v0, float v1) {
    asm volatile("red.global.add.v2.f32 [%0], {%1, %2};"
                 :: "l"(ptr), "f"(v0), "f"(v1) : "memory");
}

// ---------------- kernel 0: init out with broadcast bias --------------------
__global__ __launch_bounds__(256) void init_out_kernel(
    const float* __restrict__ bias, float* __restrict__ out)
{
    const int idx = blockIdx.x * blockDim.x + threadIdx.x;  // float4 index
    const int c4  = idx & 1023;                             // col/4 (n fastest)
    reinterpret_cast<float4*>(out)[idx] =
        reinterpret_cast<const float4*>(bias)[c4];
}

// ---------------- kernel 1: build W in fp32, store fp16 (8 elems/thread) ---
__global__ __launch_bounds__(256) void build_w_kernel(
    const float* __restrict__ a0, const float* __restrict__ a1,
    const float* __restrict__ a2, const float* __restrict__ a3,
    const float* __restrict__ a4, const float* __restrict__ a5,
    const float* __restrict__ a6, const float* __restrict__ a7,
    const float* __restrict__ b0, const float* __restrict__ b1,
    const float* __restrict__ b2, const float* __restrict__ b3,
    const float* __restrict__ b4, const float* __restrict__ b5,
    const float* __restrict__ b6, const float* __restrict__ b7)
{
    const int t = blockIdx.x * blockDim.x + threadIdx.x;  // 0 .. 2.097M-1
    const int i  = t >> 9;          // row 0..4095
    const int j0 = (t & 511) << 3;  // 8-aligned col

    const float av0 = a0[(i >> 6) * 64  + (j0 >> 6)];
    const float av1 = a1[(i >> 6) * 64  + (j0 >> 6)];
    const float av2 = a2[(i >> 7) * 32  + (j0 >> 7)];
    const float av3 = a3[(i >> 5) * 128 + (j0 >> 5)];
    const float av4 = a4[(i >> 8) * 16  + (j0 >> 8)];
    const float av5 = a5[(i >> 4) * 256 + (j0 >> 4)];
    const float av6 = a6[(i >> 9) * 8   + (j0 >> 9)];
    const float av7 = a7[(i >> 3) * 512 + (j0 >> 3)];

    const float4* p0 = reinterpret_cast<const float4*>(b0 + (i & 63)  * 64  + (j0 & 63));
    const float4* p1 = reinterpret_cast<const float4*>(b1 + (i & 63)  * 64  + (j0 & 63));
    const float4* p2 = reinterpret_cast<const float4*>(b2 + (i & 127) * 128 + (j0 & 127));
    const float4* p3 = reinterpret_cast<const float4*>(b3 + (i & 31)  * 32  + (j0 & 31));
    const float4* p4 = reinterpret_cast<const float4*>(b4 + (i & 255) * 256 + (j0 & 255));
    const float4* p5 = reinterpret_cast<const float4*>(b5 + (i & 15)  * 16  + (j0 & 15));
    const float4* p6 = reinterpret_cast<const float4*>(b6 + (i & 511) * 512 + (j0 & 511));
    const float4* p7 = reinterpret_cast<const float4*>(b7 + (i & 7)   * 8   + (j0 & 7));

    float s[8];
#pragma unroll
    for (int e = 0; e < 8; ++e) s[e] = 0.0f;

#pragma unroll
    for (int h = 0; h < 2; ++h) {
        float4 v0 = p0[h], v1 = p1[h], v2 = p2[h], v3 = p3[h];
        float4 v4 = p4[h], v5 = p5[h], v6 = p6[h], v7 = p7[h];
        float* e0 = &v0.x; float* e1 = &v1.x; float* e2 = &v2.x; float* e3 = &v3.x;
        float* e4 = &v4.x; float* e5 = &v5.x; float* e6 = &v6.x; float* e7 = &v7.x;
#pragma unroll
        for (int e = 0; e < 4; ++e) {
            float acc = av0 * e0[e];
            acc = fmaf(av1, e1[e], acc);
            acc = fmaf(av2, e2[e], acc);
            acc = fmaf(av3, e3[e], acc);
            acc = fmaf(av4, e4[e], acc);
            acc = fmaf(av5, e5[e], acc);
            acc = fmaf(av6, e6[e], acc);
            acc = fmaf(av7, e7[e], acc);
            s[h * 4 + e] = acc * 0.17677669529663687f;  // 1/(2*sqrt(8))
        }
    }

    __half h8[8];
#pragma unroll
    for (int e = 0; e < 8; ++e) h8[e] = __float2half_rn(s[e]);
    *reinterpret_cast<uint4*>(g_Wh + (size_t)i * N_DIM + j0) =
        *reinterpret_cast<uint4*>(h8);
}

// ---------------- kernel 2: convert X to fp16 -------------------------------
__global__ __launch_bounds__(256) void split_x_kernel(const float* __restrict__ x)
{
    const int i = blockIdx.x * blockDim.x + threadIdx.x;  // float4 index
    float4 v = reinterpret_cast<const float4*>(x)[i];
    __half2 h0 = __floats2half2_rn(v.x, v.y);
    __half2 h1 = __floats2half2_rn(v.z, v.w);
    reinterpret_cast<__half2*>(g_Xh)[2 * i]     = h0;
    reinterpret_cast<__half2*>(g_Xh)[2 * i + 1] = h1;
}

// ---------------- kernel 3: fp16 mma.sync GEMM (K-split 2) ------------------
// CTA tile 256(M) x 128(N), K-half = 2048 (32 ktiles of 64), 512 threads.
// SMEM: 4 stages x 48KB:
//   +0      W (256 x 64 fp16, SW128-swizzled 128B rows)  = 32KB
//   +32768  X (128 x 64 fp16)                            = 16KB
static constexpr int SM_BUFSZ   = 49152;
static constexpr int NSTAGE     = 4;
static constexpr int SMEM_TOTAL = NSTAGE * SM_BUFSZ;  // 196608
static constexpr int KTILES     = 32;                 // per K-half

__global__ __launch_bounds__(512, 1)
void gemm_kernel(float* __restrict__ out)
{
    extern __shared__ __align__(1024) char smem[];
    const uint32_t sb = smem_u32(smem);
    const int tid = threadIdx.x;
    const int wid = tid >> 5;
    const int lid = tid & 31;

    const int rbase = blockIdx.x * 256;        // M rows (W / OUTF)
    const int nbase = blockIdx.y * 128;        // N rows (X / BATCH)
    const int kbase = blockIdx.z * 2048;       // K half

    const int warp_m = wid & 3;   // 0..3 -> 64-row slab
    const int warp_n = wid >> 2;  // 0..3 -> 32-col slab

    const int lj   = lid & 7;   // row-within-8 for ldmatrix
    const int lsel = lid >> 3;  // which 8x8 matrix this lane feeds

    // ---- cp.async stage loader: 3072 chunks of 16B, 6 per thread ----------
    auto load_stage = [&](int t) {
        if (t < KTILES) {
            const uint32_t bufb = sb + (uint32_t)(t & 3) * SM_BUFSZ;
            const int k0 = kbase + t * 64;
#pragma unroll
            for (int s = 0; s < 4; ++s) {        // W: 2048 chunks (256 rows)
                const int c   = tid + s * 512;
                const int row = c >> 3;
                const int ch  = c & 7;
                const uint32_t sw =
                    SMEM_SWIZZLE_128B((uint32_t)(row * 128 + ch * 16));
                cp_async16(bufb + sw,
                           g_Wh + (size_t)(rbase + row) * N_DIM + k0 + ch * 8);
            }
#pragma unroll
            for (int s = 0; s < 2; ++s) {        // X: 1024 chunks (128 rows)
                const int c   = tid + s * 512;
                const int row = c >> 3;
                const int ch  = c & 7;
                const uint32_t sw =
                    SMEM_SWIZZLE_128B((uint32_t)(row * 128 + ch * 16));
                cp_async16(bufb + 32768 + sw,
                           g_Xh + (size_t)(nbase + row) * N_DIM + k0 + ch * 8);
            }
        }
        asm volatile("cp.async.commit_group;" ::: "memory");
    };

    // ---- accumulators: 4 m16-blocks x 4 n8-blocks x 4 regs = 64 -----------
    float d[4][4][4];
#pragma unroll
    for (int mb = 0; mb < 4; ++mb)
#pragma unroll
        for (int q = 0; q < 4; ++q)
#pragma unroll
            for (int r = 0; r < 4; ++r) d[mb][q][r] = 0.0f;

    load_stage(0);
    load_stage(1);
    load_stage(2);

    for (int t = 0; t < KTILES; ++t) {
        // stage t resident (<=2 newest groups pending)
        asm volatile("cp.async.wait_group 2;" ::: "memory");
        __syncthreads();

        load_stage(t + 3);

        const uint32_t bufb = sb + (uint32_t)(t & 3) * SM_BUFSZ;

#pragma unroll
        for (int ks = 0; ks < 4; ++ks) {
            const int kc = ks * 2;  // 16B-chunk index of this k16 step

            // A fragments (rows = M): 4 x m16
            uint32_t fA[4][4];
#pragma unroll
            for (int mb = 0; mb < 4; ++mb) {
                const int row = warp_m * 64 + mb * 16 + lj + ((lsel & 1) << 3);
                const int ch  = kc + (lsel >> 1);
                ldm_x4(fA[mb], bufb +
                       SMEM_SWIZZLE_128B((uint32_t)(row * 128 + ch * 16)));
            }

            // B fragments (rows = N): 2 x n16
            uint32_t fB[2][4];
#pragma unroll
            for (int nb = 0; nb < 2; ++nb) {
                const int row = warp_n * 32 + nb * 16 + lj + ((lsel >> 1) << 3);
                const int ch  = kc + (lsel & 1);
                ldm_x4(fB[nb], bufb + 32768 +
                       SMEM_SWIZZLE_128B((uint32_t)(row * 128 + ch * 16)));
            }

            // 16 HMMA per ks
#pragma unroll
            for (int mb = 0; mb < 4; ++mb) {
#pragma unroll
                for (int nb = 0; nb < 2; ++nb) {
                    mma_fp16(d[mb][nb * 2 + 0], fA[mb], fB[nb][0], fB[nb][1]);
                    mma_fp16(d[mb][nb * 2 + 1], fA[mb], fB[nb][2], fB[nb][3]);
                }
            }
        }
    }

    asm volatile("cp.async.wait_group 0;" ::: "memory");

    // ---- epilogue: regs -> gmem via f32 reduction (bias pre-filled) -------
    // d-frag: d0,d1 -> row (lid>>2),   cols (lid&3)*2 + {0,1}
    //         d2,d3 -> row (lid>>2)+8, same cols
    const int rw = rbase + warp_m * 64 + (lid >> 2);
    const int cw = nbase + warp_n * 32 + (lid & 3) * 2;
#pragma unroll
    for (int mb = 0; mb < 4; ++mb) {
#pragma unroll
        for (int q = 0; q < 4; ++q) {
            const int col = cw + q * 8;
            const int r0  = rw + mb * 16;
            red_add_v2(out + (size_t)r0 * N_DIM + col,
                       d[mb][q][0], d[mb][q][1]);
            red_add_v2(out + (size_t)(r0 + 8) * N_DIM + col,
                       d[mb][q][2], d[mb][q][3]);
        }
    }
}

// ---------------- launch ----------------------------------------------------
extern "C" void kernel_launch(void* const* d_in, const int* in_sizes, int n_in,
                              void* d_out, int out_size)
{
    const float* x    = (const float*)d_in[0];
    const float* a[8] = {(const float*)d_in[1], (const float*)d_in[2],
                         (const float*)d_in[3], (const float*)d_in[4],
                         (const float*)d_in[5], (const float*)d_in[6],
                         (const float*)d_in[7], (const float*)d_in[8]};
    const float* b[8] = {(const float*)d_in[9],  (const float*)d_in[10],
                         (const float*)d_in[11], (const float*)d_in[12],
                         (const float*)d_in[13], (const float*)d_in[14],
                         (const float*)d_in[15], (const float*)d_in[16]};
    const float* bias = (const float*)d_in[17];
    float* out = (float*)d_out;

    cudaFuncSetAttribute(gemm_kernel,
                         cudaFuncAttributeMaxDynamicSharedMemorySize,
                         SMEM_TOTAL);

    // 0) out = broadcast(bias)
    init_out_kernel<<<(N_DIM * N_DIM / 4) / 256, 256>>>(bias, out);

    // 1) W build (fp32 math, fp16 store): 8 outputs/thread
    build_w_kernel<<<(N_DIM * N_DIM / 8) / 256, 256>>>(
        a[0], a[1], a[2], a[3], a[4], a[5], a[6], a[7],
        b[0], b[1], b[2], b[3], b[4], b[5], b[6], b[7]);

    // 2) X -> fp16
    split_x_kernel<<<(N_DIM * N_DIM / 4) / 256, 256>>>(x);

    // 3) GEMM: 16x32x2 grid (256x128 tiles, K split in 2), 512 threads
    gemm_kernel<<<dim3(16, 32, 2), 512, SMEM_TOTAL>>>(out);
}

// round 13
// speedup vs baseline: 2.6805x; 1.0787x over previous
#include <cuda_runtime.h>
#include <cuda_bf16.h>
#include <cuda_fp16.h>
#include <cstdint>

// ============================================================================
// KLinear: y[i,n] = (sum_k kron(a_k,b_k)[i,j] / (2*sqrt(8))) * x[n,j] + bias[n]
//
// fp16 single-product GEMM (calibrated rel_err 2.93e-4), fp32 accum.
// Round-13: 2 CTAs/SM to fill tensor-pipe gaps (R12 profile: tensor=66%,
// occ=24%, 1 CTA/SM -> every ktile barrier stalls the whole SM).
//   * CTA 128x128, 256 threads (8 warps, 2Mx4N), ~110 regs -> 2 CTAs/SM
//   * 3-stage x 32KB cp.async pipeline (96KB smem/CTA; 192KB/SM)
//   * K-split 2 -> 2048 CTAs = 6.92 waves @ 296 concurrent (1.2% quant loss)
//   * out prefilled with bias; epilogue red.global.add.v2.f32
// ============================================================================

#define N_DIM 4096

// ---------------- scratch (device globals; no runtime allocation) ----------
__device__ __half g_Wh[(size_t)N_DIM * N_DIM];
__device__ __half g_Xh[(size_t)N_DIM * N_DIM];

// ---------------- helpers ---------------------------------------------------
#define SMEM_SWIZZLE_128B(o) ((o) ^ (((o) >> 3) & 0x70))

__device__ __forceinline__ uint32_t smem_u32(const void* p) {
    uint32_t a;
    asm("{ .reg .u64 t; cvta.to.shared.u64 t, %1; cvt.u32.u64 %0, t; }"
        : "=r"(a) : "l"(p));
    return a;
}

__device__ __forceinline__ void cp_async16(uint32_t dst, const void* src) {
    asm volatile("cp.async.cg.shared.global [%0], [%1], 16;"
                 :: "r"(dst), "l"(src) : "memory");
}

__device__ __forceinline__ void ldm_x4(uint32_t (&r)[4], uint32_t addr) {
    asm volatile("ldmatrix.sync.aligned.m8n8.x4.shared.b16 {%0,%1,%2,%3}, [%4];"
                 : "=r"(r[0]), "=r"(r[1]), "=r"(r[2]), "=r"(r[3])
                 : "r"(addr));
}

__device__ __forceinline__ void mma_fp16(float (&d)[4], const uint32_t (&a)[4],
                                         uint32_t b0, uint32_t b1) {
    asm volatile(
        "mma.sync.aligned.m16n8k16.row.col.f32.f16.f16.f32 "
        "{%0,%1,%2,%3}, {%4,%5,%6,%7}, {%8,%9}, {%0,%1,%2,%3};"
        : "+f"(d[0]), "+f"(d[1]), "+f"(d[2]), "+f"(d[3])
        : "r"(a[0]), "r"(a[1]), "r"(a[2]), "r"(a[3]), "r"(b0), "r"(b1));
}

__device__ __forceinline__ void red_add_v2(float* ptr, float v0, float v1) {
    asm volatile("red.global.add.v2.f32 [%0], {%1, %2};"
                 :: "l"(ptr), "f"(v0), "f"(v1) : "memory");
}

// ---------------- kernel 0: init out with broadcast bias --------------------
__global__ __launch_bounds__(256) void init_out_kernel(
    const float* __restrict__ bias, float* __restrict__ out)
{
    const int idx = blockIdx.x * blockDim.x + threadIdx.x;  // float4 index
    const int c4  = idx & 1023;                             // col/4 (n fastest)
    reinterpret_cast<float4*>(out)[idx] =
        reinterpret_cast<const float4*>(bias)[c4];
}

// ---------------- kernel 1: build W in fp32, store fp16 (8 elems/thread) ---
__global__ __launch_bounds__(256) void build_w_kernel(
    const float* __restrict__ a0, const float* __restrict__ a1,
    const float* __restrict__ a2, const float* __restrict__ a3,
    const float* __restrict__ a4, const float* __restrict__ a5,
    const float* __restrict__ a6, const float* __restrict__ a7,
    const float* __restrict__ b0, const float* __restrict__ b1,
    const float* __restrict__ b2, const float* __restrict__ b3,
    const float* __restrict__ b4, const float* __restrict__ b5,
    const float* __restrict__ b6, const float* __restrict__ b7)
{
    const int t = blockIdx.x * blockDim.x + threadIdx.x;  // 0 .. 2.097M-1
    const int i  = t >> 9;          // row 0..4095
    const int j0 = (t & 511) << 3;  // 8-aligned col

    const float av0 = a0[(i >> 6) * 64  + (j0 >> 6)];
    const float av1 = a1[(i >> 6) * 64  + (j0 >> 6)];
    const float av2 = a2[(i >> 7) * 32  + (j0 >> 7)];
    const float av3 = a3[(i >> 5) * 128 + (j0 >> 5)];
    const float av4 = a4[(i >> 8) * 16  + (j0 >> 8)];
    const float av5 = a5[(i >> 4) * 256 + (j0 >> 4)];
    const float av6 = a6[(i >> 9) * 8   + (j0 >> 9)];
    const float av7 = a7[(i >> 3) * 512 + (j0 >> 3)];

    const float4* p0 = reinterpret_cast<const float4*>(b0 + (i & 63)  * 64  + (j0 & 63));
    const float4* p1 = reinterpret_cast<const float4*>(b1 + (i & 63)  * 64  + (j0 & 63));
    const float4* p2 = reinterpret_cast<const float4*>(b2 + (i & 127) * 128 + (j0 & 127));
    const float4* p3 = reinterpret_cast<const float4*>(b3 + (i & 31)  * 32  + (j0 & 31));
    const float4* p4 = reinterpret_cast<const float4*>(b4 + (i & 255) * 256 + (j0 & 255));
    const float4* p5 = reinterpret_cast<const float4*>(b5 + (i & 15)  * 16  + (j0 & 15));
    const float4* p6 = reinterpret_cast<const float4*>(b6 + (i & 511) * 512 + (j0 & 511));
    const float4* p7 = reinterpret_cast<const float4*>(b7 + (i & 7)   * 8   + (j0 & 7));

    float s[8];
#pragma unroll
    for (int e = 0; e < 8; ++e) s[e] = 0.0f;

#pragma unroll
    for (int h = 0; h < 2; ++h) {
        float4 v0 = p0[h], v1 = p1[h], v2 = p2[h], v3 = p3[h];
        float4 v4 = p4[h], v5 = p5[h], v6 = p6[h], v7 = p7[h];
        float* e0 = &v0.x; float* e1 = &v1.x; float* e2 = &v2.x; float* e3 = &v3.x;
        float* e4 = &v4.x; float* e5 = &v5.x; float* e6 = &v6.x; float* e7 = &v7.x;
#pragma unroll
        for (int e = 0; e < 4; ++e) {
            float acc = av0 * e0[e];
            acc = fmaf(av1, e1[e], acc);
            acc = fmaf(av2, e2[e], acc);
            acc = fmaf(av3, e3[e], acc);
            acc = fmaf(av4, e4[e], acc);
            acc = fmaf(av5, e5[e], acc);
            acc = fmaf(av6, e6[e], acc);
            acc = fmaf(av7, e7[e], acc);
            s[h * 4 + e] = acc * 0.17677669529663687f;  // 1/(2*sqrt(8))
        }
    }

    __half h8[8];
#pragma unroll
    for (int e = 0; e < 8; ++e) h8[e] = __float2half_rn(s[e]);
    *reinterpret_cast<uint4*>(g_Wh + (size_t)i * N_DIM + j0) =
        *reinterpret_cast<uint4*>(h8);
}

// ---------------- kernel 2: convert X to fp16 -------------------------------
__global__ __launch_bounds__(256) void split_x_kernel(const float* __restrict__ x)
{
    const int i = blockIdx.x * blockDim.x + threadIdx.x;  // float4 index
    float4 v = reinterpret_cast<const float4*>(x)[i];
    __half2 h0 = __floats2half2_rn(v.x, v.y);
    __half2 h1 = __floats2half2_rn(v.z, v.w);
    reinterpret_cast<__half2*>(g_Xh)[2 * i]     = h0;
    reinterpret_cast<__half2*>(g_Xh)[2 * i + 1] = h1;
}

// ---------------- kernel 3: fp16 mma.sync GEMM (K-split 2, 2 CTA/SM) -------
// CTA tile 128(M) x 128(N), K-half = 2048 (32 ktiles of 64), 256 threads.
// SMEM: 3 stages x 32KB:
//   +0      W (128 x 64 fp16, SW128-swizzled 128B rows)  = 16KB
//   +16384  X (128 x 64 fp16)                            = 16KB
static constexpr int SM_BUFSZ   = 32768;
static constexpr int NSTAGE     = 3;
static constexpr int SMEM_TOTAL = NSTAGE * SM_BUFSZ;  // 98304
static constexpr int KTILES     = 32;                 // per K-half

__global__ __launch_bounds__(256, 2)
void gemm_kernel(float* __restrict__ out)
{
    extern __shared__ __align__(1024) char smem[];
    const uint32_t sb = smem_u32(smem);
    const int tid = threadIdx.x;
    const int wid = tid >> 5;
    const int lid = tid & 31;

    const int rbase = blockIdx.x * 128;        // M rows (W / OUTF)
    const int nbase = blockIdx.y * 128;        // N rows (X / BATCH)
    const int kbase = blockIdx.z * 2048;       // K half

    const int warp_m = wid & 1;   // 0..1 -> 64-row slab
    const int warp_n = wid >> 1;  // 0..3 -> 32-col slab

    const int lj   = lid & 7;   // row-within-8 for ldmatrix
    const int lsel = lid >> 3;  // which 8x8 matrix this lane feeds

    // ---- cp.async stage loader: 2048 chunks of 16B, 8 per thread ----------
    auto load_stage = [&](int t) {
        if (t < KTILES) {
            const uint32_t bufb =
                sb + (uint32_t)(t % NSTAGE) * SM_BUFSZ;
            const int k0 = kbase + t * 64;
#pragma unroll
            for (int s = 0; s < 4; ++s) {        // W: 1024 chunks (128 rows)
                const int c   = tid + s * 256;
                const int row = c >> 3;
                const int ch  = c & 7;
                const uint32_t sw =
                    SMEM_SWIZZLE_128B((uint32_t)(row * 128 + ch * 16));
                cp_async16(bufb + sw,
                           g_Wh + (size_t)(rbase + row) * N_DIM + k0 + ch * 8);
            }
#pragma unroll
            for (int s = 0; s < 4; ++s) {        // X: 1024 chunks (128 rows)
                const int c   = tid + s * 256;
                const int row = c >> 3;
                const int ch  = c & 7;
                const uint32_t sw =
                    SMEM_SWIZZLE_128B((uint32_t)(row * 128 + ch * 16));
                cp_async16(bufb + 16384 + sw,
                           g_Xh + (size_t)(nbase + row) * N_DIM + k0 + ch * 8);
            }
        }
        asm volatile("cp.async.commit_group;" ::: "memory");
    };

    // ---- accumulators: 4 m16-blocks x 4 n8-blocks x 4 regs = 64 -----------
    float d[4][4][4];
#pragma unroll
    for (int mb = 0; mb < 4; ++mb)
#pragma unroll
        for (int q = 0; q < 4; ++q)
#pragma unroll
            for (int r = 0; r < 4; ++r) d[mb][q][r] = 0.0f;

    load_stage(0);
    load_stage(1);

    for (int t = 0; t < KTILES; ++t) {
        // stage t resident (<=1 newest group pending)
        asm volatile("cp.async.wait_group 1;" ::: "memory");
        __syncthreads();

        load_stage(t + 2);

        const uint32_t bufb = sb + (uint32_t)(t % NSTAGE) * SM_BUFSZ;

#pragma unroll
        for (int ks = 0; ks < 4; ++ks) {
            const int kc = ks * 2;  // 16B-chunk index of this k16 step

            // A fragments (rows = M): 4 x m16 (64-row warp slab)
            uint32_t fA[4][4];
#pragma unroll
            for (int mb = 0; mb < 4; ++mb) {
                const int row = warp_m * 64 + mb * 16 + lj + ((lsel & 1) << 3);
                const int ch  = kc + (lsel >> 1);
                ldm_x4(fA[mb], bufb +
                       SMEM_SWIZZLE_128B((uint32_t)(row * 128 + ch * 16)));
            }

            // B fragments (rows = N): 2 x n16 (32-col warp slab)
            uint32_t fB[2][4];
#pragma unroll
            for (int nb = 0; nb < 2; ++nb) {
                const int row = warp_n * 32 + nb * 16 + lj + ((lsel >> 1) << 3);
                const int ch  = kc + (lsel & 1);
                ldm_x4(fB[nb], bufb + 16384 +
                       SMEM_SWIZZLE_128B((uint32_t)(row * 128 + ch * 16)));
            }

            // 16 HMMA per ks
#pragma unroll
            for (int mb = 0; mb < 4; ++mb) {
#pragma unroll
                for (int nb = 0; nb < 2; ++nb) {
                    mma_fp16(d[mb][nb * 2 + 0], fA[mb], fB[nb][0], fB[nb][1]);
                    mma_fp16(d[mb][nb * 2 + 1], fA[mb], fB[nb][2], fB[nb][3]);
                }
            }
        }
    }

    asm volatile("cp.async.wait_group 0;" ::: "memory");

    // ---- epilogue: regs -> gmem via f32 reduction (bias pre-filled) -------
    // d-frag: d0,d1 -> row (lid>>2),   cols (lid&3)*2 + {0,1}
    //         d2,d3 -> row (lid>>2)+8, same cols
    const int rw = rbase + warp_m * 64 + (lid >> 2);
    const int cw = nbase + warp_n * 32 + (lid & 3) * 2;
#pragma unroll
    for (int mb = 0; mb < 4; ++mb) {
#pragma unroll
        for (int q = 0; q < 4; ++q) {
            const int col = cw + q * 8;
            const int r0  = rw + mb * 16;
            red_add_v2(out + (size_t)r0 * N_DIM + col,
                       d[mb][q][0], d[mb][q][1]);
            red_add_v2(out + (size_t)(r0 + 8) * N_DIM + col,
                       d[mb][q][2], d[mb][q][3]);
        }
    }
}

// ---------------- launch ----------------------------------------------------
extern "C" void kernel_launch(void* const* d_in, const int* in_sizes, int n_in,
                              void* d_out, int out_size)
{
    const float* x    = (const float*)d_in[0];
    const float* a[8] = {(const float*)d_in[1], (const float*)d_in[2],
                         (const float*)d_in[3], (const float*)d_in[4],
                         (const float*)d_in[5], (const float*)d_in[6],
                         (const float*)d_in[7], (const float*)d_in[8]};
    const float* b[8] = {(const float*)d_in[9],  (const float*)d_in[10],
                         (const float*)d_in[11], (const float*)d_in[12],
                         (const float*)d_in[13], (const float*)d_in[14],
                         (const float*)d_in[15], (const float*)d_in[16]};
    const float* bias = (const float*)d_in[17];
    float* out = (float*)d_out;

    cudaFuncSetAttribute(gemm_kernel,
                         cudaFuncAttributeMaxDynamicSharedMemorySize,
                         SMEM_TOTAL);

    // 0) out = broadcast(bias)
    init_out_kernel<<<(N_DIM * N_DIM / 4) / 256, 256>>>(bias, out);

    // 1) W build (fp32 math, fp16 store): 8 outputs/thread
    build_w_kernel<<<(N_DIM * N_DIM / 8) / 256, 256>>>(
        a[0], a[1], a[2], a[3], a[4], a[5], a[6], a[7],
        b[0], b[1], b[2], b[3], b[4], b[5], b[6], b[7]);

    // 2) X -> fp16
    split_x_kernel<<<(N_DIM * N_DIM / 4) / 256, 256>>>(x);

    // 3) GEMM: 32x32x2 grid (128x128 tiles, K split in 2), 256 threads
    gemm_kernel<<<dim3(32, 32, 2), 256, SMEM_TOTAL>>>(out);
}

// round 14
// speedup vs baseline: 2.7255x; 1.0168x over previous
#include <cuda_runtime.h>
#include <cuda_bf16.h>
#include <cuda_fp16.h>
#include <cstdint>

// ============================================================================
// KLinear: y[i,n] = (sum_k kron(a_k,b_k)[i,j] / (2*sqrt(8))) * x[n,j] + bias[n]
//
// fp16 single-product GEMM (calibrated rel_err 2.93e-4), fp32 accum.
// Round-14: 64x64 warp tiles to unbind the smem crossbar (R13 accounting:
// LDSM+cp traffic 2048 cyc vs tensor 1843 cyc per ktile-pair at 64x32).
//   * CTA 128x128, 128 threads (4 warps, 2Mx2N), warp tile 64x64
//     -> LDSM bytes/MAC halved; smem 1536 cyc < tensor 1843 cyc
//   * 3-stage x 32KB pipeline, 96KB smem/CTA -> 2 CTAs/SM (two barrier
//     domains), regs free up to 256 -> no pressure, deep ptxas scheduling
//   * K-split 2 -> 2048 CTAs = 6.92 waves (1.2% quant loss)
//   * out prefilled with bias; epilogue red.global.add.v2.f32
// ============================================================================

#define N_DIM 4096

// ---------------- scratch (device globals; no runtime allocation) ----------
__device__ __half g_Wh[(size_t)N_DIM * N_DIM];
__device__ __half g_Xh[(size_t)N_DIM * N_DIM];

// ---------------- helpers ---------------------------------------------------
#define SMEM_SWIZZLE_128B(o) ((o) ^ (((o) >> 3) & 0x70))

__device__ __forceinline__ uint32_t smem_u32(const void* p) {
    uint32_t a;
    asm("{ .reg .u64 t; cvta.to.shared.u64 t, %1; cvt.u32.u64 %0, t; }"
        : "=r"(a) : "l"(p));
    return a;
}

__device__ __forceinline__ void cp_async16(uint32_t dst, const void* src) {
    asm volatile("cp.async.cg.shared.global [%0], [%1], 16;"
                 :: "r"(dst), "l"(src) : "memory");
}

__device__ __forceinline__ void ldm_x4(uint32_t (&r)[4], uint32_t addr) {
    asm volatile("ldmatrix.sync.aligned.m8n8.x4.shared.b16 {%0,%1,%2,%3}, [%4];"
                 : "=r"(r[0]), "=r"(r[1]), "=r"(r[2]), "=r"(r[3])
                 : "r"(addr));
}

__device__ __forceinline__ void mma_fp16(float (&d)[4], const uint32_t (&a)[4],
                                         uint32_t b0, uint32_t b1) {
    asm volatile(
        "mma.sync.aligned.m16n8k16.row.col.f32.f16.f16.f32 "
        "{%0,%1,%2,%3}, {%4,%5,%6,%7}, {%8,%9}, {%0,%1,%2,%3};"
        : "+f"(d[0]), "+f"(d[1]), "+f"(d[2]), "+f"(d[3])
        : "r"(a[0]), "r"(a[1]), "r"(a[2]), "r"(a[3]), "r"(b0), "r"(b1));
}

__device__ __forceinline__ void red_add_v2(float* ptr, float v0, float v1) {
    asm volatile("red.global.add.v2.f32 [%0], {%1, %2};"
                 :: "l"(ptr), "f"(v0), "f"(v1) : "memory");
}

// ---------------- kernel 0: init out with broadcast bias --------------------
__global__ __launch_bounds__(256) void init_out_kernel(
    const float* __restrict__ bias, float* __restrict__ out)
{
    const int idx = blockIdx.x * blockDim.x + threadIdx.x;  // float4 index
    const int c4  = idx & 1023;                             // col/4 (n fastest)
    reinterpret_cast<float4*>(out)[idx] =
        reinterpret_cast<const float4*>(bias)[c4];
}

// ---------------- kernel 1: build W in fp32, store fp16 (8 elems/thread) ---
__global__ __launch_bounds__(256) void build_w_kernel(
    const float* __restrict__ a0, const float* __restrict__ a1,
    const float* __restrict__ a2, const float* __restrict__ a3,
    const float* __restrict__ a4, const float* __restrict__ a5,
    const float* __restrict__ a6, const float* __restrict__ a7,
    const float* __restrict__ b0, const float* __restrict__ b1,
    const float* __restrict__ b2, const float* __restrict__ b3,
    const float* __restrict__ b4, const float* __restrict__ b5,
    const float* __restrict__ b6, const float* __restrict__ b7)
{
    const int t = blockIdx.x * blockDim.x + threadIdx.x;  // 0 .. 2.097M-1
    const int i  = t >> 9;          // row 0..4095
    const int j0 = (t & 511) << 3;  // 8-aligned col

    const float av0 = a0[(i >> 6) * 64  + (j0 >> 6)];
    const float av1 = a1[(i >> 6) * 64  + (j0 >> 6)];
    const float av2 = a2[(i >> 7) * 32  + (j0 >> 7)];
    const float av3 = a3[(i >> 5) * 128 + (j0 >> 5)];
    const float av4 = a4[(i >> 8) * 16  + (j0 >> 8)];
    const float av5 = a5[(i >> 4) * 256 + (j0 >> 4)];
    const float av6 = a6[(i >> 9) * 8   + (j0 >> 9)];
    const float av7 = a7[(i >> 3) * 512 + (j0 >> 3)];

    const float4* p0 = reinterpret_cast<const float4*>(b0 + (i & 63)  * 64  + (j0 & 63));
    const float4* p1 = reinterpret_cast<const float4*>(b1 + (i & 63)  * 64  + (j0 & 63));
    const float4* p2 = reinterpret_cast<const float4*>(b2 + (i & 127) * 128 + (j0 & 127));
    const float4* p3 = reinterpret_cast<const float4*>(b3 + (i & 31)  * 32  + (j0 & 31));
    const float4* p4 = reinterpret_cast<const float4*>(b4 + (i & 255) * 256 + (j0 & 255));
    const float4* p5 = reinterpret_cast<const float4*>(b5 + (i & 15)  * 16  + (j0 & 15));
    const float4* p6 = reinterpret_cast<const float4*>(b6 + (i & 511) * 512 + (j0 & 511));
    const float4* p7 = reinterpret_cast<const float4*>(b7 + (i & 7)   * 8   + (j0 & 7));

    float s[8];
#pragma unroll
    for (int e = 0; e < 8; ++e) s[e] = 0.0f;

#pragma unroll
    for (int h = 0; h < 2; ++h) {
        float4 v0 = p0[h], v1 = p1[h], v2 = p2[h], v3 = p3[h];
        float4 v4 = p4[h], v5 = p5[h], v6 = p6[h], v7 = p7[h];
        float* e0 = &v0.x; float* e1 = &v1.x; float* e2 = &v2.x; float* e3 = &v3.x;
        float* e4 = &v4.x; float* e5 = &v5.x; float* e6 = &v6.x; float* e7 = &v7.x;
#pragma unroll
        for (int e = 0; e < 4; ++e) {
            float acc = av0 * e0[e];
            acc = fmaf(av1, e1[e], acc);
            acc = fmaf(av2, e2[e], acc);
            acc = fmaf(av3, e3[e], acc);
            acc = fmaf(av4, e4[e], acc);
            acc = fmaf(av5, e5[e], acc);
            acc = fmaf(av6, e6[e], acc);
            acc = fmaf(av7, e7[e], acc);
            s[h * 4 + e] = acc * 0.17677669529663687f;  // 1/(2*sqrt(8))
        }
    }

    __half h8[8];
#pragma unroll
    for (int e = 0; e < 8; ++e) h8[e] = __float2half_rn(s[e]);
    *reinterpret_cast<uint4*>(g_Wh + (size_t)i * N_DIM + j0) =
        *reinterpret_cast<uint4*>(h8);
}

// ---------------- kernel 2: convert X to fp16 -------------------------------
__global__ __launch_bounds__(256) void split_x_kernel(const float* __restrict__ x)
{
    const int i = blockIdx.x * blockDim.x + threadIdx.x;  // float4 index
    float4 v = reinterpret_cast<const float4*>(x)[i];
    __half2 h0 = __floats2half2_rn(v.x, v.y);
    __half2 h1 = __floats2half2_rn(v.z, v.w);
    reinterpret_cast<__half2*>(g_Xh)[2 * i]     = h0;
    reinterpret_cast<__half2*>(g_Xh)[2 * i + 1] = h1;
}

// ---------------- kernel 3: fp16 mma.sync GEMM ------------------------------
// CTA tile 128(M) x 128(N), K-half = 2048 (32 ktiles of 64), 128 threads
// (4 warps, 2Mx2N, warp tile 64x64). SMEM: 3 stages x 32KB:
//   +0      W (128 x 64 fp16, SW128-swizzled 128B rows)  = 16KB
//   +16384  X (128 x 64 fp16)                            = 16KB
static constexpr int SM_BUFSZ   = 32768;
static constexpr int NSTAGE     = 3;
static constexpr int SMEM_TOTAL = NSTAGE * SM_BUFSZ;  // 98304
static constexpr int KTILES     = 32;                 // per K-half

__global__ __launch_bounds__(128, 2)
void gemm_kernel(float* __restrict__ out)
{
    extern __shared__ __align__(1024) char smem[];
    const uint32_t sb = smem_u32(smem);
    const int tid = threadIdx.x;
    const int wid = tid >> 5;
    const int lid = tid & 31;

    const int rbase = blockIdx.x * 128;        // M rows (W / OUTF)
    const int nbase = blockIdx.y * 128;        // N rows (X / BATCH)
    const int kbase = blockIdx.z * 2048;       // K half

    const int warp_m = wid & 1;   // 0..1 -> 64-row slab
    const int warp_n = wid >> 1;  // 0..1 -> 64-col slab

    const int lj   = lid & 7;   // row-within-8 for ldmatrix
    const int lsel = lid >> 3;  // which 8x8 matrix this lane feeds

    // ---- cp.async stage loader: 2048 chunks of 16B, 16 per thread ---------
    auto load_stage = [&](int t) {
        if (t < KTILES) {
            const uint32_t bufb =
                sb + (uint32_t)(t % NSTAGE) * SM_BUFSZ;
            const int k0 = kbase + t * 64;
#pragma unroll
            for (int s = 0; s < 8; ++s) {        // W: 1024 chunks (128 rows)
                const int c   = tid + s * 128;
                const int row = c >> 3;
                const int ch  = c & 7;
                const uint32_t sw =
                    SMEM_SWIZZLE_128B((uint32_t)(row * 128 + ch * 16));
                cp_async16(bufb + sw,
                           g_Wh + (size_t)(rbase + row) * N_DIM + k0 + ch * 8);
            }
#pragma unroll
            for (int s = 0; s < 8; ++s) {        // X: 1024 chunks (128 rows)
                const int c   = tid + s * 128;
                const int row = c >> 3;
                const int ch  = c & 7;
                const uint32_t sw =
                    SMEM_SWIZZLE_128B((uint32_t)(row * 128 + ch * 16));
                cp_async16(bufb + 16384 + sw,
                           g_Xh + (size_t)(nbase + row) * N_DIM + k0 + ch * 8);
            }
        }
        asm volatile("cp.async.commit_group;" ::: "memory");
    };

    // ---- accumulators: 4 m16-blocks x 8 n8-blocks x 4 regs = 128 ----------
    float d[4][8][4];
#pragma unroll
    for (int mb = 0; mb < 4; ++mb)
#pragma unroll
        for (int q = 0; q < 8; ++q)
#pragma unroll
            for (int r = 0; r < 4; ++r) d[mb][q][r] = 0.0f;

    load_stage(0);
    load_stage(1);

    for (int t = 0; t < KTILES; ++t) {
        // stage t resident (<=1 newest group pending)
        asm volatile("cp.async.wait_group 1;" ::: "memory");
        __syncthreads();

        load_stage(t + 2);

        const uint32_t bufb = sb + (uint32_t)(t % NSTAGE) * SM_BUFSZ;

#pragma unroll
        for (int ks = 0; ks < 4; ++ks) {
            const int kc = ks * 2;  // 16B-chunk index of this k16 step

            // A fragments (rows = M): 4 x m16 (64-row warp slab)
            uint32_t fA[4][4];
#pragma unroll
            for (int mb = 0; mb < 4; ++mb) {
                const int row = warp_m * 64 + mb * 16 + lj + ((lsel & 1) << 3);
                const int ch  = kc + (lsel >> 1);
                ldm_x4(fA[mb], bufb +
                       SMEM_SWIZZLE_128B((uint32_t)(row * 128 + ch * 16)));
            }

            // B fragments (rows = N): 4 x n16 (64-col warp slab)
            uint32_t fB[4][4];
#pragma unroll
            for (int nb = 0; nb < 4; ++nb) {
                const int row = warp_n * 64 + nb * 16 + lj + ((lsel >> 1) << 3);
                const int ch  = kc + (lsel & 1);
                ldm_x4(fB[nb], bufb + 16384 +
                       SMEM_SWIZZLE_128B((uint32_t)(row * 128 + ch * 16)));
            }

            // 32 HMMA per ks
#pragma unroll
            for (int mb = 0; mb < 4; ++mb) {
#pragma unroll
                for (int nb = 0; nb < 4; ++nb) {
                    mma_fp16(d[mb][nb * 2 + 0], fA[mb], fB[nb][0], fB[nb][1]);
                    mma_fp16(d[mb][nb * 2 + 1], fA[mb], fB[nb][2], fB[nb][3]);
                }
            }
        }
    }

    asm volatile("cp.async.wait_group 0;" ::: "memory");

    // ---- epilogue: regs -> gmem via f32 reduction (bias pre-filled) -------
    // d-frag: d0,d1 -> row (lid>>2),   cols (lid&3)*2 + {0,1}
    //         d2,d3 -> row (lid>>2)+8, same cols
    const int rw = rbase + warp_m * 64 + (lid >> 2);
    const int cw = nbase + warp_n * 64 + (lid & 3) * 2;
#pragma unroll
    for (int mb = 0; mb < 4; ++mb) {
#pragma unroll
        for (int q = 0; q < 8; ++q) {
            const int col = cw + q * 8;
            const int r0  = rw + mb * 16;
            red_add_v2(out + (size_t)r0 * N_DIM + col,
                       d[mb][q][0], d[mb][q][1]);
            red_add_v2(out + (size_t)(r0 + 8) * N_DIM + col,
                       d[mb][q][2], d[mb][q][3]);
        }
    }
}

// ---------------- launch ----------------------------------------------------
extern "C" void kernel_launch(void* const* d_in, const int* in_sizes, int n_in,
                              void* d_out, int out_size)
{
    const float* x    = (const float*)d_in[0];
    const float* a[8] = {(const float*)d_in[1], (const float*)d_in[2],
                         (const float*)d_in[3], (const float*)d_in[4],
                         (const float*)d_in[5], (const float*)d_in[6],
                         (const float*)d_in[7], (const float*)d_in[8]};
    const float* b[8] = {(const float*)d_in[9],  (const float*)d_in[10],
                         (const float*)d_in[11], (const float*)d_in[12],
                         (const float*)d_in[13], (const float*)d_in[14],
                         (const float*)d_in[15], (const float*)d_in[16]};
    const float* bias = (const float*)d_in[17];
    float* out = (float*)d_out;

    cudaFuncSetAttribute(gemm_kernel,
                         cudaFuncAttributeMaxDynamicSharedMemorySize,
                         SMEM_TOTAL);

    // 0) out = broadcast(bias)
    init_out_kernel<<<(N_DIM * N_DIM / 4) / 256, 256>>>(bias, out);

    // 1) W build (fp32 math, fp16 store): 8 outputs/thread
    build_w_kernel<<<(N_DIM * N_DIM / 8) / 256, 256>>>(
        a[0], a[1], a[2], a[3], a[4], a[5], a[6], a[7],
        b[0], b[1], b[2], b[3], b[4], b[5], b[6], b[7]);

    // 2) X -> fp16
    split_x_kernel<<<(N_DIM * N_DIM / 4) / 256, 256>>>(x);

    // 3) GEMM: 32x32x2 grid (128x128 tiles, K split in 2), 128 threads
    gemm_kernel<<<dim3(32, 32, 2), 128, SMEM_TOTAL>>>(out);
}